// round 13
// baseline (speedup 1.0000x reference)
#include <cuda_runtime.h>
#include <cuda_fp16.h>
#include <math.h>
#include <stdint.h>

#define Bb   2
#define Ss   4096
#define Hh   512
#define NHh  8
#define HDd  64
#define QKV3 1536
#define TOK  (Bb * Ss)          // 8192

typedef unsigned long long u64;
typedef unsigned int u32;
typedef unsigned short u16;

// ============================================================================
// Global scratch (allocation-free rule: __device__ globals), all split fp16
// ============================================================================
__device__ u16 xs_hi[(size_t)TOK * Hh],  xs_lo[(size_t)TOK * Hh];
__device__ u16 wq_hi[(size_t)QKV3 * Hh], wq_lo[(size_t)QKV3 * Hh];
__device__ u16 wo_hi[(size_t)Hh * Hh],   wo_lo[(size_t)Hh * Hh];
// per (b,h): q,k [4096,64] row-major ; vt [64,4096] d-major
__device__ u16 q_hi [(size_t)16 * Ss * HDd], q_lo [(size_t)16 * Ss * HDd];
__device__ u16 k_hi [(size_t)16 * Ss * HDd], k_lo [(size_t)16 * Ss * HDd];
__device__ u16 vt_hi[(size_t)16 * Ss * HDd], vt_lo[(size_t)16 * Ss * HDd];
__device__ u16 att_hi[(size_t)TOK * Hh], att_lo[(size_t)TOK * Hh];
// split-KV partials for heavy queries (q < 256): 9 slots x 16 bh x 256 q
#define HQ 256
__device__ float part_o[(size_t)9 * 16 * HQ * 64];
__device__ float part_m[9 * 16 * HQ];
__device__ float part_l[9 * 16 * HQ];

// ============================================================================
// helpers
// ============================================================================
__device__ __forceinline__ u32 smem_u32(const void* p) {
    u32 a;
    asm("{ .reg .u64 t; cvta.to.shared.u64 t, %1; cvt.u32.u64 %0, t; }"
        : "=r"(a) : "l"(p));
    return a;
}
// split (a, b) into hi (packed f16x2: a->lo, b->hi) and lo residual pack
__device__ __forceinline__ void split2_f16(float a, float b, u32& hi, u32& lo) {
    __half2 hp = __floats2half2_rn(a, b);
    float ra = a - __half2float(__low2half(hp));
    float rb = b - __half2float(__high2half(hp));
    __half2 lp = __floats2half2_rn(ra, rb);
    hi = *reinterpret_cast<u32*>(&hp);
    lo = *reinterpret_cast<u32*>(&lp);
}
// fp32-accumulate mma (half rate if accumulator-gimp hypothesis true)
__device__ __forceinline__ void mma_f16(float* d, const u32* a, const u32* b) {
    asm volatile(
        "mma.sync.aligned.m16n8k16.row.col.f32.f16.f16.f32 "
        "{%0,%1,%2,%3}, {%4,%5,%6,%7}, {%8,%9}, {%0,%1,%2,%3};"
        : "+f"(d[0]), "+f"(d[1]), "+f"(d[2]), "+f"(d[3])
        : "r"(a[0]), "r"(a[1]), "r"(a[2]), "r"(a[3]), "r"(b[0]), "r"(b[1]));
}
// fp16-accumulate mma (full rate) — used for residual passes only
__device__ __forceinline__ void mma_h(u32* d, const u32* a, const u32* b) {
    asm volatile(
        "mma.sync.aligned.m16n8k16.row.col.f16.f16.f16.f16 "
        "{%0,%1}, {%2,%3,%4,%5}, {%6,%7}, {%0,%1};"
        : "+r"(d[0]), "+r"(d[1])
        : "r"(a[0]), "r"(a[1]), "r"(a[2]), "r"(a[3]), "r"(b[0]), "r"(b[1]));
}
// fold f16 accumulator pair (4 halves = one n-block C fragment) into f32
__device__ __forceinline__ void fold_h(float* sf, const u32* hacc) {
    float2 x0 = __half22float2(*reinterpret_cast<const __half2*>(&hacc[0]));
    float2 x1 = __half22float2(*reinterpret_cast<const __half2*>(&hacc[1]));
    sf[0] += x0.x; sf[1] += x0.y; sf[2] += x1.x; sf[3] += x1.y;
}
__device__ __forceinline__ void ldsm4(u32* r, u32 addr) {
    asm volatile("ldmatrix.sync.aligned.m8n8.x4.shared.b16 {%0,%1,%2,%3}, [%4];"
        : "=r"(r[0]), "=r"(r[1]), "=r"(r[2]), "=r"(r[3]) : "r"(addr));
}
#define CP16(s, g) \
    asm volatile("cp.async.cg.shared.global [%0], [%1], 16;" \
                 :: "r"(s), "l"(g) : "memory")
#define CP_COMMIT() asm volatile("cp.async.commit_group;" ::: "memory")
#define CP_WAIT0()  asm volatile("cp.async.wait_group 0;" ::: "memory")
#define CP_WAIT1()  asm volatile("cp.async.wait_group 1;" ::: "memory")

// ============================================================================
// split kernel: fp32 -> (hi fp16, lo fp16)
// ============================================================================
__global__ void split_pair(const float* __restrict__ src,
                           u16* __restrict__ hi, u16* __restrict__ lo, int n2)
{
    int i = blockIdx.x * blockDim.x + threadIdx.x;
    if (i >= n2) return;
    float a = src[2 * i], b = src[2 * i + 1];
    u32 h, l;
    split2_f16(a, b, h, l);
    ((u32*)hi)[i] = h;
    ((u32*)lo)[i] = l;
}

// ============================================================================
// GEMM on mma.sync: C[M,N] = A[M,512] @ B[N,512]^T, split-fp16 3-pass.
// hi*hi -> f32 accum; lo*hi + hi*lo -> f16 accum (full-rate), folded at end.
// 128x64 tile, BK=64, 256 threads / 8 warps. cp.async double-buffered.
// ============================================================================
#define RB 144
#define G_AHI 0u
#define G_ALO 18432u
#define G_BHI 36864u
#define G_BLO 46080u
#define G_BUF 55296u
#define GEMM_SMEM 110592

template<int MODE>
__global__ __launch_bounds__(256, 2) void gemm_mma(
    const u16* __restrict__ Ah, const u16* __restrict__ Al,
    const u16* __restrict__ Bh, const u16* __restrict__ Bl,
    const float* __restrict__ bias, float* __restrict__ Cf,
    int M, int N, int K)
{
    extern __shared__ char sm[];
    const u32 smb = smem_u32(sm);
    const int tid = threadIdx.x;
    const int wid = tid >> 5;
    const int lid = tid & 31;
    const int g   = lid >> 2;
    const int qd  = lid & 3;
    const int m0  = blockIdx.y * 128;
    const int n0  = blockIdx.x * 64;

    const u32 a_row   = (u32)(16 * wid + (lid & 15));
    const u32 a_col16 = (u32)(((lid >> 4) & 1) << 4);
    const u32 aOffA   = a_row * RB + a_col16;
    const u32 bOff4 = (u32)((lid & 7) * RB + (((lid >> 3) & 1) << 4)
                            + (((lid >> 4) & 1) * 8 * RB));

    const int sr  = tid >> 3;
    const int sc  = tid & 7;

    float sf[8][4];
    u32 hacc[16];
    #pragma unroll
    for (int n = 0; n < 8; n++) {
        #pragma unroll
        for (int e = 0; e < 4; e++) sf[n][e] = 0.f;
        hacc[2*n] = 0u; hacc[2*n+1] = 0u;
    }

    // prefetch chunk 0 into buffer 0
    {
        const u32 base = smb;
        #pragma unroll
        for (int i = 0; i < 4; i++) {
            int row = sr + i * 32;
            CP16(base + G_AHI + row * RB + sc * 16, &Ah[(size_t)(m0 + row) * K + sc * 8]);
            CP16(base + G_ALO + row * RB + sc * 16, &Al[(size_t)(m0 + row) * K + sc * 8]);
        }
        #pragma unroll
        for (int i = 0; i < 2; i++) {
            int row = sr + i * 32;
            CP16(base + G_BHI + row * RB + sc * 16, &Bh[(size_t)(n0 + row) * K + sc * 8]);
            CP16(base + G_BLO + row * RB + sc * 16, &Bl[(size_t)(n0 + row) * K + sc * 8]);
        }
        CP_COMMIT();
    }

    const int nk = K >> 6;
    for (int ck = 0; ck < nk; ck++) {
        const u32 cbase = smb + (u32)(ck & 1) * G_BUF;
        if (ck + 1 < nk) {
            const u32 nbase = smb + (u32)((ck + 1) & 1) * G_BUF;
            const int kc = (ck + 1) << 6;
            #pragma unroll
            for (int i = 0; i < 4; i++) {
                int row = sr + i * 32;
                CP16(nbase + G_AHI + row * RB + sc * 16, &Ah[(size_t)(m0 + row) * K + kc + sc * 8]);
                CP16(nbase + G_ALO + row * RB + sc * 16, &Al[(size_t)(m0 + row) * K + kc + sc * 8]);
            }
            #pragma unroll
            for (int i = 0; i < 2; i++) {
                int row = sr + i * 32;
                CP16(nbase + G_BHI + row * RB + sc * 16, &Bh[(size_t)(n0 + row) * K + kc + sc * 8]);
                CP16(nbase + G_BLO + row * RB + sc * 16, &Bl[(size_t)(n0 + row) * K + kc + sc * 8]);
            }
            CP_COMMIT();
            CP_WAIT1();
        } else {
            CP_WAIT0();
        }
        __syncthreads();

        #pragma unroll
        for (int k = 0; k < 4; k++) {
            u32 ah[4], al[4];
            ldsm4(ah, cbase + G_AHI + aOffA + k * 32);
            ldsm4(al, cbase + G_ALO + aOffA + k * 32);
            #pragma unroll
            for (int q = 0; q < 4; q++) {
                u32 bh4[4], bl4[4];
                u32 ba = cbase + G_BHI + (u32)(q * 16 * RB) + bOff4 + k * 32;
                ldsm4(bh4, ba);
                ldsm4(bl4, ba + (G_BLO - G_BHI));
                mma_f16(sf[2*q],     ah, bh4);        // hi*hi -> f32
                mma_f16(sf[2*q + 1], ah, bh4 + 2);
                mma_h(hacc + 4*q,     al, bh4);       // lo*hi -> f16
                mma_h(hacc + 4*q + 2, al, bh4 + 2);
                mma_h(hacc + 4*q,     ah, bl4);       // hi*lo -> f16
                mma_h(hacc + 4*q + 2, ah, bl4 + 2);
            }
        }
        __syncthreads();
    }

    // fold f16 residual accumulators into f32
    #pragma unroll
    for (int n = 0; n < 8; n++) fold_h(sf[n], hacc + 2*n);

    if (MODE == 1) {
        const int row0 = m0 + 16 * wid + g;
        #pragma unroll
        for (int n = 0; n < 8; n++) {
            const int cg = n0 + 8 * n + 2 * qd;
            float bx = bias[cg], by = bias[cg + 1];
            *(float2*)&Cf[(size_t)row0 * N + cg] =
                make_float2(sf[n][0] + bx, sf[n][1] + by);
            *(float2*)&Cf[(size_t)(row0 + 8) * N + cg] =
                make_float2(sf[n][2] + bx, sf[n][3] + by);
        }
    } else {
        const float scale = (n0 < 512) ? 0.125f : 1.0f;
        const int prow0 = 16 * wid + g;
        #pragma unroll
        for (int n = 0; n < 8; n++) {
            float a0 = sf[n][0] * scale, a1 = sf[n][1] * scale;
            float a2 = sf[n][2] * scale, a3 = sf[n][3] * scale;
            u32 h0, l0, h1, l1;
            split2_f16(a0, a1, h0, l0);
            split2_f16(a2, a3, h1, l1);
            u32 cb = (u32)(16 * n + 4 * qd);
            *(u32*)(sm + G_AHI + (u32)(prow0 * RB) + cb)       = h0;
            *(u32*)(sm + G_AHI + (u32)((prow0 + 8) * RB) + cb) = h1;
            *(u32*)(sm + G_ALO + (u32)(prow0 * RB) + cb)       = l0;
            *(u32*)(sm + G_ALO + (u32)((prow0 + 8) * RB) + cb) = l1;
        }
        __syncthreads();

        const int type = n0 >> 9;                      // 0=q 1=k 2=v
        const int bhd  = (m0 >> 12) * 8 + ((n0 & 511) >> 6);
        const int s0   = m0 & 4095;

        if (type < 2) {
            u16* dh = (type == 0) ? q_hi : k_hi;
            u16* dl = (type == 0) ? q_lo : k_lo;
            #pragma unroll
            for (int i = 0; i < 4; i++) {
                int row = sr + i * 32;
                size_t d = ((size_t)bhd * Ss + s0 + row) * 64 + sc * 8;
                *(uint4*)&dh[d] = *(uint4*)(sm + G_AHI + row * RB + sc * 16);
                *(uint4*)&dl[d] = *(uint4*)(sm + G_ALO + row * RB + sc * 16);
            }
        } else {
            #pragma unroll
            for (int i = 0; i < 4; i++) {
                int t  = tid + i * 256;
                int d  = t >> 4, ch = t & 15;
                u16 th[8], tl[8];
                #pragma unroll
                for (int j = 0; j < 8; j++) {
                    int s = ch * 8 + j;
                    th[j] = *(u16*)(sm + G_AHI + s * RB + d * 2);
                    tl[j] = *(u16*)(sm + G_ALO + s * RB + d * 2);
                }
                size_t dst = ((size_t)bhd * 64 + d) * Ss + s0 + ch * 8;
                *(uint4*)&vt_hi[dst] = *(uint4*)th;
                *(uint4*)&vt_lo[dst] = *(uint4*)tl;
            }
        }
    }
}

// ============================================================================
// Flash attention on mma.sync (fp16 split, f16-accum residual passes),
// banded + split-KV, single merged launch. Bounds as round 11.
// ============================================================================
#define OFF_KHI  0u
#define OFF_KLO  9216u
#define OFF_VTHI 18432u
#define OFF_VTLO 27648u
#define OFF_QHI  36864u
#define OFF_QLO  55296u
#define ATTN_SMEM 73728

__global__ __launch_bounds__(256, 2) void attn_mma()
{
    extern __shared__ char sm[];
    const u32 smb = smem_u32(sm);
    const int tid = threadIdx.x;
    const int wid = tid >> 5;
    const int lid = tid & 31;
    const int g   = lid >> 2;
    const int qd  = lid & 3;

    int qb, kb0, kb1, slot;
    if (blockIdx.x < 32) {
        qb = blockIdx.x; kb0 = 0; kb1 = HQ; slot = 0;
    } else {
        const int t = blockIdx.x - 32;
        qb = t >> 3;
        const int c = t & 7;
        const int t0 = (c < 4) ? (4 + 8 * c) : (36 + 7 * (c - 4));
        const int t1 = t0 + ((c < 4) ? 8 : 7);
        kb0 = t0 * 64; kb1 = t1 * 64; slot = 1 + c;
    }
    const int qbase = qb * 128;
    const int h = blockIdx.y;
    const int b = blockIdx.z;
    const int bhd = b * 8 + h;

    const u16* qgh = q_hi + (size_t)bhd * Ss * 64;
    const u16* qgl = q_lo + (size_t)bhd * Ss * 64;
    const u16* kgh = k_hi + (size_t)bhd * Ss * 64;
    const u16* kgl = k_lo + (size_t)bhd * Ss * 64;
    const u16* vgh = vt_hi + (size_t)bhd * 64 * Ss;
    const u16* vgl = vt_lo + (size_t)bhd * 64 * Ss;

    const int sr = tid >> 3;
    const int sc = tid & 7;

    // ---- Q staging (cp.async, once) ----
    #pragma unroll
    for (int i = 0; i < 4; i++) {
        int row = sr + i * 32;
        size_t s = (size_t)(qbase + row) * 64 + sc * 8;
        CP16(smb + OFF_QHI + row * RB + sc * 16, &qgh[s]);
        CP16(smb + OFF_QLO + row * RB + sc * 16, &qgl[s]);
    }

    const u32 a_row   = (u32)(16 * wid + (lid & 15));
    const u32 a_col16 = (u32)(((lid >> 4) & 1) << 4);
    const u32 aQhi = smb + OFF_QHI + a_row * RB + a_col16;
    const u32 aQlo = smb + OFF_QLO + a_row * RB + a_col16;
    const u32 bOff4 = (u32)((lid & 7) * RB + (((lid >> 3) & 1) << 4)
                            + (((lid >> 4) & 1) * 8 * RB));

    float o[8][4];
    #pragma unroll
    for (int n = 0; n < 8; n++)
        #pragma unroll
        for (int e = 0; e < 4; e++) o[n][e] = 0.f;
    float m0 = -1e30f, m1 = -1e30f, l0 = 0.f, l1 = 0.f;
    const float LOGD = -0.10536051565782628f;   // log(0.9)
    const int iq0 = qbase + 16 * wid + g;

    for (int kb = kb0; kb < kb1; kb += 64) {
        #pragma unroll
        for (int i = 0; i < 2; i++) {
            int row = sr + i * 32;
            size_t sk = (size_t)(kb + row) * 64 + sc * 8;
            CP16(smb + OFF_KHI + row * RB + sc * 16, &kgh[sk]);
            CP16(smb + OFF_KLO + row * RB + sc * 16, &kgl[sk]);
            size_t sv = (size_t)row * Ss + kb + sc * 8;
            CP16(smb + OFF_VTHI + row * RB + sc * 16, &vgh[sv]);
            CP16(smb + OFF_VTLO + row * RB + sc * 16, &vgl[sv]);
        }
        CP_COMMIT();
        CP_WAIT0();
        __syncthreads();

        // ---- S = Q K^T : hi*hi f32 + residuals f16 ----
        float sf[8][4];
        u32 hacc[16];
        #pragma unroll
        for (int n = 0; n < 8; n++) {
            #pragma unroll
            for (int e = 0; e < 4; e++) sf[n][e] = 0.f;
            hacc[2*n] = 0u; hacc[2*n+1] = 0u;
        }

        #pragma unroll
        for (int k = 0; k < 4; k++) {
            u32 ah[4], al[4];
            ldsm4(ah, aQhi + k * 32);
            ldsm4(al, aQlo + k * 32);
            #pragma unroll
            for (int q = 0; q < 4; q++) {
                u32 bh4[4], bl4[4];
                u32 ba = smb + OFF_KHI + (u32)(q * 16 * RB) + bOff4 + k * 32;
                ldsm4(bh4, ba);
                ldsm4(bl4, ba + (OFF_KLO - OFF_KHI));
                mma_f16(sf[2*q],     ah, bh4);
                mma_f16(sf[2*q + 1], ah, bh4 + 2);
                mma_h(hacc + 4*q,     al, bh4);
                mma_h(hacc + 4*q + 2, al, bh4 + 2);
                mma_h(hacc + 4*q,     ah, bl4);
                mma_h(hacc + 4*q + 2, ah, bl4 + 2);
            }
        }
        #pragma unroll
        for (int n = 0; n < 8; n++) fold_h(sf[n], hacc + 2*n);

        // ---- bias + online softmax ----
        const float base0 = (float)(kb - iq0);
        float rmax0 = -1e30f, rmax1 = -1e30f;
        #pragma unroll
        for (int n = 0; n < 8; n++) {
            #pragma unroll
            for (int e = 0; e < 2; e++) {
                float c = (float)(8 * n + 2 * qd + e);
                float t0 = sf[n][e]     + fmaxf((base0 + c) * LOGD, 0.0f);
                float t1 = sf[n][2 + e] + fmaxf((base0 - 8.0f + c) * LOGD, 0.0f);
                sf[n][e] = t0; sf[n][2 + e] = t1;
                rmax0 = fmaxf(rmax0, t0);
                rmax1 = fmaxf(rmax1, t1);
            }
        }
        rmax0 = fmaxf(rmax0, __shfl_xor_sync(0xffffffffu, rmax0, 1));
        rmax0 = fmaxf(rmax0, __shfl_xor_sync(0xffffffffu, rmax0, 2));
        rmax1 = fmaxf(rmax1, __shfl_xor_sync(0xffffffffu, rmax1, 1));
        rmax1 = fmaxf(rmax1, __shfl_xor_sync(0xffffffffu, rmax1, 2));

        float mn0 = fmaxf(m0, rmax0), mn1 = fmaxf(m1, rmax1);
        float corr0 = __expf(m0 - mn0), corr1 = __expf(m1 - mn1);
        m0 = mn0; m1 = mn1;

        float rs0 = 0.f, rs1 = 0.f;
        #pragma unroll
        for (int n = 0; n < 8; n++) {
            sf[n][0] = __expf(sf[n][0] - mn0);
            sf[n][1] = __expf(sf[n][1] - mn0);
            sf[n][2] = __expf(sf[n][2] - mn1);
            sf[n][3] = __expf(sf[n][3] - mn1);
            rs0 += sf[n][0] + sf[n][1];
            rs1 += sf[n][2] + sf[n][3];
        }
        rs0 += __shfl_xor_sync(0xffffffffu, rs0, 1);
        rs0 += __shfl_xor_sync(0xffffffffu, rs0, 2);
        rs1 += __shfl_xor_sync(0xffffffffu, rs1, 1);
        rs1 += __shfl_xor_sync(0xffffffffu, rs1, 2);
        l0 = l0 * corr0 + rs0;
        l1 = l1 * corr1 + rs1;

        #pragma unroll
        for (int n = 0; n < 8; n++) {
            o[n][0] *= corr0; o[n][1] *= corr0;
            o[n][2] *= corr1; o[n][3] *= corr1;
        }

        // ---- O += P V : hi*hi f32 into o, residuals f16 per tile ----
        #pragma unroll
        for (int n = 0; n < 8; n++) { hacc[2*n] = 0u; hacc[2*n+1] = 0u; }
        #pragma unroll
        for (int kk = 0; kk < 4; kk++) {
            u32 ph[4], pl[4];
            split2_f16(sf[2*kk][0],   sf[2*kk][1],   ph[0], pl[0]);
            split2_f16(sf[2*kk][2],   sf[2*kk][3],   ph[1], pl[1]);
            split2_f16(sf[2*kk+1][0], sf[2*kk+1][1], ph[2], pl[2]);
            split2_f16(sf[2*kk+1][2], sf[2*kk+1][3], ph[3], pl[3]);
            #pragma unroll
            for (int q = 0; q < 4; q++) {
                u32 vh4[4], vl4[4];
                u32 ba = smb + OFF_VTHI + (u32)(q * 16 * RB) + bOff4 + kk * 32;
                ldsm4(vh4, ba);
                ldsm4(vl4, ba + (OFF_VTLO - OFF_VTHI));
                mma_f16(o[2*q],     ph, vh4);
                mma_f16(o[2*q + 1], ph, vh4 + 2);
                mma_h(hacc + 4*q,     pl, vh4);
                mma_h(hacc + 4*q + 2, pl, vh4 + 2);
                mma_h(hacc + 4*q,     ph, vl4);
                mma_h(hacc + 4*q + 2, ph, vl4 + 2);
            }
        }
        #pragma unroll
        for (int n = 0; n < 8; n++) fold_h(o[n], hacc + 2*n);
        __syncthreads();
    }

    if (blockIdx.x < 32 && qbase >= HQ) {
        // ---- final: normalize, split, write att hi/lo ----
        const float inv0 = 1.0f / l0, inv1 = 1.0f / l1;
        const size_t r0 = ((size_t)(b * Ss + iq0)) * Hh + h * HDd;
        const size_t r1 = r0 + (size_t)8 * Hh;
        #pragma unroll
        for (int n = 0; n < 8; n++) {
            int col = 8 * n + 2 * qd;
            u32 h0, l0w, h1, l1w;
            split2_f16(o[n][0] * inv0, o[n][1] * inv0, h0, l0w);
            split2_f16(o[n][2] * inv1, o[n][3] * inv1, h1, l1w);
            *(u32*)&att_hi[r0 + col] = h0;
            *(u32*)&att_lo[r0 + col] = l0w;
            *(u32*)&att_hi[r1 + col] = h1;
            *(u32*)&att_lo[r1 + col] = l1w;
        }
    } else {
        // ---- partial: write unnormalized o + (m, l) to slot ----
        const size_t rb0 = ((size_t)(slot * 16 + bhd) * HQ + iq0) * 64;
        const size_t rb1 = rb0 + (size_t)8 * 64;
        #pragma unroll
        for (int n = 0; n < 8; n++) {
            int col = 8 * n + 2 * qd;
            *(float2*)&part_o[rb0 + col] = make_float2(o[n][0], o[n][1]);
            *(float2*)&part_o[rb1 + col] = make_float2(o[n][2], o[n][3]);
        }
        if (qd == 0) {
            const int mi = (slot * 16 + bhd) * HQ + iq0;
            part_m[mi]     = m0; part_l[mi]     = l0;
            part_m[mi + 8] = m1; part_l[mi + 8] = l1;
        }
    }
}

// ============================================================================
// combine 9 split-KV partials per heavy query row -> att hi/lo
// grid (HQ, 16), block 64 (one thread per dim)
// ============================================================================
__global__ void combine_partials()
{
    const int q   = blockIdx.x;
    const int bhd = blockIdx.y;
    const int d   = threadIdx.x;

    float mm[9], ll[9];
    float M = -1e30f;
    #pragma unroll
    for (int s = 0; s < 9; s++) {
        mm[s] = part_m[(s * 16 + bhd) * HQ + q];
        ll[s] = part_l[(s * 16 + bhd) * HQ + q];
        M = fmaxf(M, mm[s]);
    }
    float L = 0.f, acc = 0.f;
    #pragma unroll
    for (int s = 0; s < 9; s++) {
        float e = __expf(mm[s] - M);
        L += ll[s] * e;
        acc += part_o[((size_t)(s * 16 + bhd) * HQ + q) * 64 + d] * e;
    }
    float a = acc / L;

    const int b = bhd >> 3, h = bhd & 7;
    const size_t idx = ((size_t)(b * Ss + q)) * Hh + h * HDd + d;
    __half hh = __float2half_rn(a);
    float r = a - __half2float(hh);
    att_hi[idx] = __half_as_ushort(hh);
    att_lo[idx] = __half_as_ushort(__float2half_rn(r));
}

// ============================================================================

extern "C" void kernel_launch(void* const* d_in, const int* in_sizes, int n_in,
                              void* d_out, int out_size)
{
    const float* x     = (const float*)d_in[0];
    const float* w_qkv = (const float*)d_in[1];
    const float* w_out = (const float*)d_in[2];
    const float* b_out = (const float*)d_in[3];
    float* out = (float*)d_out;

    u16 *p_xs_hi, *p_xs_lo, *p_wq_hi, *p_wq_lo, *p_wo_hi, *p_wo_lo;
    u16 *p_att_hi, *p_att_lo;
    cudaGetSymbolAddress((void**)&p_xs_hi, xs_hi);
    cudaGetSymbolAddress((void**)&p_xs_lo, xs_lo);
    cudaGetSymbolAddress((void**)&p_wq_hi, wq_hi);
    cudaGetSymbolAddress((void**)&p_wq_lo, wq_lo);
    cudaGetSymbolAddress((void**)&p_wo_hi, wo_hi);
    cudaGetSymbolAddress((void**)&p_wo_lo, wo_lo);
    cudaGetSymbolAddress((void**)&p_att_hi, att_hi);
    cudaGetSymbolAddress((void**)&p_att_lo, att_lo);

    cudaFuncSetAttribute(attn_mma,
                         cudaFuncAttributeMaxDynamicSharedMemorySize, ATTN_SMEM);
    cudaFuncSetAttribute(gemm_mma<0>,
                         cudaFuncAttributeMaxDynamicSharedMemorySize, GEMM_SMEM);
    cudaFuncSetAttribute(gemm_mma<1>,
                         cudaFuncAttributeMaxDynamicSharedMemorySize, GEMM_SMEM);

    // 0) split inputs into hi/lo fp16
    {
        int n2 = TOK * Hh / 2;
        split_pair<<<(n2 + 255) / 256, 256>>>(x, p_xs_hi, p_xs_lo, n2);
        n2 = QKV3 * Hh / 2;
        split_pair<<<(n2 + 255) / 256, 256>>>(w_qkv, p_wq_hi, p_wq_lo, n2);
        n2 = Hh * Hh / 2;
        split_pair<<<(n2 + 255) / 256, 256>>>(w_out, p_wo_hi, p_wo_lo, n2);
    }

    // 1) qkv projection -> split q/k (row-major) + vt (transposed)
    gemm_mma<0><<<dim3(QKV3 / 64, TOK / 128), 256, GEMM_SMEM>>>(
        p_xs_hi, p_xs_lo, p_wq_hi, p_wq_lo, nullptr, nullptr, TOK, QKV3, Hh);

    // 2) merged banded + split-KV attention (one launch)
    attn_mma<<<dim3(32 + 2 * 8, NHh, Bb), 256, ATTN_SMEM>>>();
    // 2c) combine partials for heavy queries
    combine_partials<<<dim3(HQ, 16), 64>>>();

    // 3) out projection + bias
    gemm_mma<1><<<dim3(Hh / 64, TOK / 128), 256, GEMM_SMEM>>>(
        p_att_hi, p_att_lo, p_wo_hi, p_wo_lo, b_out, out, TOK, Hh, Hh);
}

// round 14
// speedup vs baseline: 1.1654x; 1.1654x over previous
#include <cuda_runtime.h>
#include <cuda_fp16.h>
#include <math.h>
#include <stdint.h>

#define Bb   2
#define Ss   4096
#define Hh   512
#define NHh  8
#define HDd  64
#define QKV3 1536
#define TOK  (Bb * Ss)          // 8192

typedef unsigned long long u64;
typedef unsigned int u32;
typedef unsigned short u16;

// ============================================================================
// Global scratch (allocation-free rule: __device__ globals), split fp16
// (k and vt are hi-only: attention uses them unsplit)
// ============================================================================
__device__ u16 xs_hi[(size_t)TOK * Hh],  xs_lo[(size_t)TOK * Hh];
__device__ u16 wq_hi[(size_t)QKV3 * Hh], wq_lo[(size_t)QKV3 * Hh];
__device__ u16 wo_hi[(size_t)Hh * Hh],   wo_lo[(size_t)Hh * Hh];
// per (b,h): q [4096,64] row-major split ; k [4096,64] hi ; vt [64,4096] hi
__device__ u16 q_hi [(size_t)16 * Ss * HDd], q_lo [(size_t)16 * Ss * HDd];
__device__ u16 k_hi [(size_t)16 * Ss * HDd];
__device__ u16 vt_hi[(size_t)16 * Ss * HDd];
__device__ u16 att_hi[(size_t)TOK * Hh], att_lo[(size_t)TOK * Hh];
// split-KV partials for heavy queries (q < 256): 9 slots x 16 bh x 256 q
#define HQ 256
__device__ float part_o[(size_t)9 * 16 * HQ * 64];
__device__ float part_m[9 * 16 * HQ];
__device__ float part_l[9 * 16 * HQ];

// ============================================================================
// helpers
// ============================================================================
__device__ __forceinline__ u32 smem_u32(const void* p) {
    u32 a;
    asm("{ .reg .u64 t; cvta.to.shared.u64 t, %1; cvt.u32.u64 %0, t; }"
        : "=r"(a) : "l"(p));
    return a;
}
// split (a, b) into hi (packed f16x2: a->lo, b->hi) and lo residual pack
__device__ __forceinline__ void split2_f16(float a, float b, u32& hi, u32& lo) {
    __half2 hp = __floats2half2_rn(a, b);
    float ra = a - __half2float(__low2half(hp));
    float rb = b - __half2float(__high2half(hp));
    __half2 lp = __floats2half2_rn(ra, rb);
    hi = *reinterpret_cast<u32*>(&hp);
    lo = *reinterpret_cast<u32*>(&lp);
}
__device__ __forceinline__ void mma_f16(float* d, const u32* a, const u32* b) {
    asm volatile(
        "mma.sync.aligned.m16n8k16.row.col.f32.f16.f16.f32 "
        "{%0,%1,%2,%3}, {%4,%5,%6,%7}, {%8,%9}, {%0,%1,%2,%3};"
        : "+f"(d[0]), "+f"(d[1]), "+f"(d[2]), "+f"(d[3])
        : "r"(a[0]), "r"(a[1]), "r"(a[2]), "r"(a[3]), "r"(b[0]), "r"(b[1]));
}
__device__ __forceinline__ void ldsm4(u32* r, u32 addr) {
    asm volatile("ldmatrix.sync.aligned.m8n8.x4.shared.b16 {%0,%1,%2,%3}, [%4];"
        : "=r"(r[0]), "=r"(r[1]), "=r"(r[2]), "=r"(r[3]) : "r"(addr));
}
#define CP16(s, g) \
    asm volatile("cp.async.cg.shared.global [%0], [%1], 16;" \
                 :: "r"(s), "l"(g) : "memory")
#define CP_COMMIT() asm volatile("cp.async.commit_group;" ::: "memory")
#define CP_WAIT0()  asm volatile("cp.async.wait_group 0;" ::: "memory")
#define CP_WAIT1()  asm volatile("cp.async.wait_group 1;" ::: "memory")

// ============================================================================
// split kernel: fp32 -> (hi fp16, lo fp16)
// ============================================================================
__global__ void split_pair(const float* __restrict__ src,
                           u16* __restrict__ hi, u16* __restrict__ lo, int n2)
{
    int i = blockIdx.x * blockDim.x + threadIdx.x;
    if (i >= n2) return;
    float a = src[2 * i], b = src[2 * i + 1];
    u32 h, l;
    split2_f16(a, b, h, l);
    ((u32*)hi)[i] = h;
    ((u32*)lo)[i] = l;
}

// ============================================================================
// GEMM on mma.sync: C[M,N] = A[M,512] @ B[N,512]^T, split-fp16 3-pass (exact).
// 128x64 tile, BK=64, 256 threads / 8 warps. cp.async double-buffered.
// MODE 0: qkv epilogue -> q split / k hi-only / vt hi-only (transposed)
// MODE 1: fp32 out + bias
// ============================================================================
#define RB 144
#define G_AHI 0u
#define G_ALO 18432u
#define G_BHI 36864u
#define G_BLO 46080u
#define G_BUF 55296u
#define GEMM_SMEM 110592

template<int MODE>
__global__ __launch_bounds__(256, 2) void gemm_mma(
    const u16* __restrict__ Ah, const u16* __restrict__ Al,
    const u16* __restrict__ Bh, const u16* __restrict__ Bl,
    const float* __restrict__ bias, float* __restrict__ Cf,
    int M, int N, int K)
{
    extern __shared__ char sm[];
    const u32 smb = smem_u32(sm);
    const int tid = threadIdx.x;
    const int wid = tid >> 5;
    const int lid = tid & 31;
    const int g   = lid >> 2;
    const int qd  = lid & 3;
    const int m0  = blockIdx.y * 128;
    const int n0  = blockIdx.x * 64;

    const u32 a_row   = (u32)(16 * wid + (lid & 15));
    const u32 a_col16 = (u32)(((lid >> 4) & 1) << 4);
    const u32 aOffA   = a_row * RB + a_col16;
    const u32 bOff4 = (u32)((lid & 7) * RB + (((lid >> 3) & 1) << 4)
                            + (((lid >> 4) & 1) * 8 * RB));

    const int sr  = tid >> 3;
    const int sc  = tid & 7;

    float sf[8][4];
    #pragma unroll
    for (int n = 0; n < 8; n++)
        #pragma unroll
        for (int e = 0; e < 4; e++) sf[n][e] = 0.f;

    // prefetch chunk 0 into buffer 0
    {
        const u32 base = smb;
        #pragma unroll
        for (int i = 0; i < 4; i++) {
            int row = sr + i * 32;
            CP16(base + G_AHI + row * RB + sc * 16, &Ah[(size_t)(m0 + row) * K + sc * 8]);
            CP16(base + G_ALO + row * RB + sc * 16, &Al[(size_t)(m0 + row) * K + sc * 8]);
        }
        #pragma unroll
        for (int i = 0; i < 2; i++) {
            int row = sr + i * 32;
            CP16(base + G_BHI + row * RB + sc * 16, &Bh[(size_t)(n0 + row) * K + sc * 8]);
            CP16(base + G_BLO + row * RB + sc * 16, &Bl[(size_t)(n0 + row) * K + sc * 8]);
        }
        CP_COMMIT();
    }

    const int nk = K >> 6;
    for (int ck = 0; ck < nk; ck++) {
        const u32 cbase = smb + (u32)(ck & 1) * G_BUF;
        if (ck + 1 < nk) {
            const u32 nbase = smb + (u32)((ck + 1) & 1) * G_BUF;
            const int kc = (ck + 1) << 6;
            #pragma unroll
            for (int i = 0; i < 4; i++) {
                int row = sr + i * 32;
                CP16(nbase + G_AHI + row * RB + sc * 16, &Ah[(size_t)(m0 + row) * K + kc + sc * 8]);
                CP16(nbase + G_ALO + row * RB + sc * 16, &Al[(size_t)(m0 + row) * K + kc + sc * 8]);
            }
            #pragma unroll
            for (int i = 0; i < 2; i++) {
                int row = sr + i * 32;
                CP16(nbase + G_BHI + row * RB + sc * 16, &Bh[(size_t)(n0 + row) * K + kc + sc * 8]);
                CP16(nbase + G_BLO + row * RB + sc * 16, &Bl[(size_t)(n0 + row) * K + kc + sc * 8]);
            }
            CP_COMMIT();
            CP_WAIT1();
        } else {
            CP_WAIT0();
        }
        __syncthreads();

        #pragma unroll
        for (int k = 0; k < 4; k++) {
            u32 ah[4], al[4];
            ldsm4(ah, cbase + G_AHI + aOffA + k * 32);
            ldsm4(al, cbase + G_ALO + aOffA + k * 32);
            u32 bh[16], bl[16];
            #pragma unroll
            for (int q = 0; q < 4; q++)
                ldsm4(bh + 4 * q, cbase + G_BHI + (u32)(q * 16 * RB) + bOff4 + k * 32);
            #pragma unroll
            for (int q = 0; q < 4; q++)
                ldsm4(bl + 4 * q, cbase + G_BLO + (u32)(q * 16 * RB) + bOff4 + k * 32);
            #pragma unroll
            for (int n = 0; n < 8; n++) mma_f16(sf[n], ah, bh + 2 * n);
            #pragma unroll
            for (int n = 0; n < 8; n++) mma_f16(sf[n], al, bh + 2 * n);
            #pragma unroll
            for (int n = 0; n < 8; n++) mma_f16(sf[n], ah, bl + 2 * n);
        }
        __syncthreads();
    }

    if (MODE == 1) {
        const int row0 = m0 + 16 * wid + g;
        #pragma unroll
        for (int n = 0; n < 8; n++) {
            const int cg = n0 + 8 * n + 2 * qd;
            float bx = bias[cg], by = bias[cg + 1];
            *(float2*)&Cf[(size_t)row0 * N + cg] =
                make_float2(sf[n][0] + bx, sf[n][1] + by);
            *(float2*)&Cf[(size_t)(row0 + 8) * N + cg] =
                make_float2(sf[n][2] + bx, sf[n][3] + by);
        }
    } else {
        const float scale = (n0 < 512) ? 0.125f : 1.0f;
        const int prow0 = 16 * wid + g;
        #pragma unroll
        for (int n = 0; n < 8; n++) {
            float a0 = sf[n][0] * scale, a1 = sf[n][1] * scale;
            float a2 = sf[n][2] * scale, a3 = sf[n][3] * scale;
            u32 h0, l0, h1, l1;
            split2_f16(a0, a1, h0, l0);
            split2_f16(a2, a3, h1, l1);
            u32 cb = (u32)(16 * n + 4 * qd);
            *(u32*)(sm + G_AHI + (u32)(prow0 * RB) + cb)       = h0;
            *(u32*)(sm + G_AHI + (u32)((prow0 + 8) * RB) + cb) = h1;
            *(u32*)(sm + G_ALO + (u32)(prow0 * RB) + cb)       = l0;
            *(u32*)(sm + G_ALO + (u32)((prow0 + 8) * RB) + cb) = l1;
        }
        __syncthreads();

        const int type = n0 >> 9;                      // 0=q 1=k 2=v
        const int bhd  = (m0 >> 12) * 8 + ((n0 & 511) >> 6);
        const int s0   = m0 & 4095;

        if (type == 0) {
            #pragma unroll
            for (int i = 0; i < 4; i++) {
                int row = sr + i * 32;
                size_t d = ((size_t)bhd * Ss + s0 + row) * 64 + sc * 8;
                *(uint4*)&q_hi[d] = *(uint4*)(sm + G_AHI + row * RB + sc * 16);
                *(uint4*)&q_lo[d] = *(uint4*)(sm + G_ALO + row * RB + sc * 16);
            }
        } else if (type == 1) {
            #pragma unroll
            for (int i = 0; i < 4; i++) {
                int row = sr + i * 32;
                size_t d = ((size_t)bhd * Ss + s0 + row) * 64 + sc * 8;
                *(uint4*)&k_hi[d] = *(uint4*)(sm + G_AHI + row * RB + sc * 16);
            }
        } else {
            #pragma unroll
            for (int i = 0; i < 4; i++) {
                int t  = tid + i * 256;
                int d  = t >> 4, ch = t & 15;
                u16 th[8];
                #pragma unroll
                for (int j = 0; j < 8; j++) {
                    int s = ch * 8 + j;
                    th[j] = *(u16*)(sm + G_AHI + s * RB + d * 2);
                }
                size_t dst = ((size_t)bhd * 64 + d) * Ss + s0 + ch * 8;
                *(uint4*)&vt_hi[dst] = *(uint4*)th;
            }
        }
    }
}

// ============================================================================
// Flash attention on mma.sync, banded + split-KV, single merged launch.
// Precision plan: q split (2-pass QK), P split (2-pass PV), K and V unsplit
// fp16 (each injects ~2.8e-4 rms; GEMMs stay 3-pass-exact).
// Bounds as round 11: band j<256 (4 tiles); heavy queries i<256 (qb 0,1).
// SMEM: KHI 0 (9216)  VTHI 9216 (9216)  QHI 18432  QLO 36864  tot 55296
// ============================================================================
#define OFF_KHI  0u
#define OFF_VTHI 9216u
#define OFF_QHI  18432u
#define OFF_QLO  36864u
#define ATTN_SMEM 55296

__global__ __launch_bounds__(256, 2) void attn_mma()
{
    extern __shared__ char sm[];
    const u32 smb = smem_u32(sm);
    const int tid = threadIdx.x;
    const int wid = tid >> 5;
    const int lid = tid & 31;
    const int g   = lid >> 2;
    const int qd  = lid & 3;

    int qb, kb0, kb1, slot;
    if (blockIdx.x < 32) {
        qb = blockIdx.x; kb0 = 0; kb1 = HQ; slot = 0;
    } else {
        const int t = blockIdx.x - 32;
        qb = t >> 3;
        const int c = t & 7;
        const int t0 = (c < 4) ? (4 + 8 * c) : (36 + 7 * (c - 4));
        const int t1 = t0 + ((c < 4) ? 8 : 7);
        kb0 = t0 * 64; kb1 = t1 * 64; slot = 1 + c;
    }
    const int qbase = qb * 128;
    const int h = blockIdx.y;
    const int b = blockIdx.z;
    const int bhd = b * 8 + h;

    const u16* qgh = q_hi + (size_t)bhd * Ss * 64;
    const u16* qgl = q_lo + (size_t)bhd * Ss * 64;
    const u16* kgh = k_hi + (size_t)bhd * Ss * 64;
    const u16* vgh = vt_hi + (size_t)bhd * 64 * Ss;

    const int sr = tid >> 3;
    const int sc = tid & 7;

    // ---- Q staging (cp.async, once) ----
    #pragma unroll
    for (int i = 0; i < 4; i++) {
        int row = sr + i * 32;
        size_t s = (size_t)(qbase + row) * 64 + sc * 8;
        CP16(smb + OFF_QHI + row * RB + sc * 16, &qgh[s]);
        CP16(smb + OFF_QLO + row * RB + sc * 16, &qgl[s]);
    }

    const u32 a_row   = (u32)(16 * wid + (lid & 15));
    const u32 a_col16 = (u32)(((lid >> 4) & 1) << 4);
    const u32 aQhi = smb + OFF_QHI + a_row * RB + a_col16;
    const u32 aQlo = smb + OFF_QLO + a_row * RB + a_col16;
    const u32 bOff4 = (u32)((lid & 7) * RB + (((lid >> 3) & 1) << 4)
                            + (((lid >> 4) & 1) * 8 * RB));

    float o[8][4];
    #pragma unroll
    for (int n = 0; n < 8; n++)
        #pragma unroll
        for (int e = 0; e < 4; e++) o[n][e] = 0.f;
    float m0 = -1e30f, m1 = -1e30f, l0 = 0.f, l1 = 0.f;
    const float LOGD = -0.10536051565782628f;   // log(0.9)
    const int iq0 = qbase + 16 * wid + g;

    for (int kb = kb0; kb < kb1; kb += 64) {
        // ---- K / VT staging (hi-only) ----
        #pragma unroll
        for (int i = 0; i < 2; i++) {
            int row = sr + i * 32;
            CP16(smb + OFF_KHI + row * RB + sc * 16,
                 &kgh[(size_t)(kb + row) * 64 + sc * 8]);
            CP16(smb + OFF_VTHI + row * RB + sc * 16,
                 &vgh[(size_t)row * Ss + kb + sc * 8]);
        }
        CP_COMMIT();
        CP_WAIT0();
        __syncthreads();

        // ---- S = Q K^T : 2 passes (qh*k + ql*k) ----
        float sf[8][4];
        #pragma unroll
        for (int n = 0; n < 8; n++)
            #pragma unroll
            for (int e = 0; e < 4; e++) sf[n][e] = 0.f;

        #pragma unroll
        for (int k = 0; k < 4; k++) {
            u32 ah[4], al[4];
            ldsm4(ah, aQhi + k * 32);
            ldsm4(al, aQlo + k * 32);
            u32 bh[16];
            #pragma unroll
            for (int q = 0; q < 4; q++)
                ldsm4(bh + 4 * q, smb + OFF_KHI + (u32)(q * 16 * RB) + bOff4 + k * 32);
            #pragma unroll
            for (int n = 0; n < 8; n++) mma_f16(sf[n], ah, bh + 2 * n);
            #pragma unroll
            for (int n = 0; n < 8; n++) mma_f16(sf[n], al, bh + 2 * n);
        }

        // ---- bias + online softmax ----
        const float base0 = (float)(kb - iq0);
        float rmax0 = -1e30f, rmax1 = -1e30f;
        #pragma unroll
        for (int n = 0; n < 8; n++) {
            #pragma unroll
            for (int e = 0; e < 2; e++) {
                float c = (float)(8 * n + 2 * qd + e);
                float t0 = sf[n][e]     + fmaxf((base0 + c) * LOGD, 0.0f);
                float t1 = sf[n][2 + e] + fmaxf((base0 - 8.0f + c) * LOGD, 0.0f);
                sf[n][e] = t0; sf[n][2 + e] = t1;
                rmax0 = fmaxf(rmax0, t0);
                rmax1 = fmaxf(rmax1, t1);
            }
        }
        rmax0 = fmaxf(rmax0, __shfl_xor_sync(0xffffffffu, rmax0, 1));
        rmax0 = fmaxf(rmax0, __shfl_xor_sync(0xffffffffu, rmax0, 2));
        rmax1 = fmaxf(rmax1, __shfl_xor_sync(0xffffffffu, rmax1, 1));
        rmax1 = fmaxf(rmax1, __shfl_xor_sync(0xffffffffu, rmax1, 2));

        float mn0 = fmaxf(m0, rmax0), mn1 = fmaxf(m1, rmax1);
        float corr0 = __expf(m0 - mn0), corr1 = __expf(m1 - mn1);
        m0 = mn0; m1 = mn1;

        float rs0 = 0.f, rs1 = 0.f;
        #pragma unroll
        for (int n = 0; n < 8; n++) {
            sf[n][0] = __expf(sf[n][0] - mn0);
            sf[n][1] = __expf(sf[n][1] - mn0);
            sf[n][2] = __expf(sf[n][2] - mn1);
            sf[n][3] = __expf(sf[n][3] - mn1);
            rs0 += sf[n][0] + sf[n][1];
            rs1 += sf[n][2] + sf[n][3];
        }
        rs0 += __shfl_xor_sync(0xffffffffu, rs0, 1);
        rs0 += __shfl_xor_sync(0xffffffffu, rs0, 2);
        rs1 += __shfl_xor_sync(0xffffffffu, rs1, 1);
        rs1 += __shfl_xor_sync(0xffffffffu, rs1, 2);
        l0 = l0 * corr0 + rs0;
        l1 = l1 * corr1 + rs1;

        #pragma unroll
        for (int n = 0; n < 8; n++) {
            o[n][0] *= corr0; o[n][1] *= corr0;
            o[n][2] *= corr1; o[n][3] *= corr1;
        }

        // ---- O += P V : 2 passes (ph*v + pl*v), V unsplit ----
        #pragma unroll
        for (int kk = 0; kk < 4; kk++) {
            u32 ph[4], pl[4];
            split2_f16(sf[2*kk][0],   sf[2*kk][1],   ph[0], pl[0]);
            split2_f16(sf[2*kk][2],   sf[2*kk][3],   ph[1], pl[1]);
            split2_f16(sf[2*kk+1][0], sf[2*kk+1][1], ph[2], pl[2]);
            split2_f16(sf[2*kk+1][2], sf[2*kk+1][3], ph[3], pl[3]);
            u32 vh[16];
            #pragma unroll
            for (int q = 0; q < 4; q++)
                ldsm4(vh + 4 * q, smb + OFF_VTHI + (u32)(q * 16 * RB) + bOff4 + kk * 32);
            #pragma unroll
            for (int n = 0; n < 8; n++) mma_f16(o[n], ph, vh + 2 * n);
            #pragma unroll
            for (int n = 0; n < 8; n++) mma_f16(o[n], pl, vh + 2 * n);
        }
        __syncthreads();
    }

    if (blockIdx.x < 32 && qbase >= HQ) {
        // ---- final: normalize, split, write att hi/lo ----
        const float inv0 = 1.0f / l0, inv1 = 1.0f / l1;
        const size_t r0 = ((size_t)(b * Ss + iq0)) * Hh + h * HDd;
        const size_t r1 = r0 + (size_t)8 * Hh;
        #pragma unroll
        for (int n = 0; n < 8; n++) {
            int col = 8 * n + 2 * qd;
            u32 h0, l0w, h1, l1w;
            split2_f16(o[n][0] * inv0, o[n][1] * inv0, h0, l0w);
            split2_f16(o[n][2] * inv1, o[n][3] * inv1, h1, l1w);
            *(u32*)&att_hi[r0 + col] = h0;
            *(u32*)&att_lo[r0 + col] = l0w;
            *(u32*)&att_hi[r1 + col] = h1;
            *(u32*)&att_lo[r1 + col] = l1w;
        }
    } else {
        // ---- partial: write unnormalized o + (m, l) to slot ----
        const size_t rb0 = ((size_t)(slot * 16 + bhd) * HQ + iq0) * 64;
        const size_t rb1 = rb0 + (size_t)8 * 64;
        #pragma unroll
        for (int n = 0; n < 8; n++) {
            int col = 8 * n + 2 * qd;
            *(float2*)&part_o[rb0 + col] = make_float2(o[n][0], o[n][1]);
            *(float2*)&part_o[rb1 + col] = make_float2(o[n][2], o[n][3]);
        }
        if (qd == 0) {
            const int mi = (slot * 16 + bhd) * HQ + iq0;
            part_m[mi]     = m0; part_l[mi]     = l0;
            part_m[mi + 8] = m1; part_l[mi + 8] = l1;
        }
    }
}

// ============================================================================
// combine 9 split-KV partials per heavy query row -> att hi/lo
// grid (HQ, 16), block 64 (one thread per dim)
// ============================================================================
__global__ void combine_partials()
{
    const int q   = blockIdx.x;
    const int bhd = blockIdx.y;
    const int d   = threadIdx.x;

    float mm[9], ll[9];
    float M = -1e30f;
    #pragma unroll
    for (int s = 0; s < 9; s++) {
        mm[s] = part_m[(s * 16 + bhd) * HQ + q];
        ll[s] = part_l[(s * 16 + bhd) * HQ + q];
        M = fmaxf(M, mm[s]);
    }
    float L = 0.f, acc = 0.f;
    #pragma unroll
    for (int s = 0; s < 9; s++) {
        float e = __expf(mm[s] - M);
        L += ll[s] * e;
        acc += part_o[((size_t)(s * 16 + bhd) * HQ + q) * 64 + d] * e;
    }
    float a = acc / L;

    const int b = bhd >> 3, h = bhd & 7;
    const size_t idx = ((size_t)(b * Ss + q)) * Hh + h * HDd + d;
    __half hh = __float2half_rn(a);
    float r = a - __half2float(hh);
    att_hi[idx] = __half_as_ushort(hh);
    att_lo[idx] = __half_as_ushort(__float2half_rn(r));
}

// ============================================================================

extern "C" void kernel_launch(void* const* d_in, const int* in_sizes, int n_in,
                              void* d_out, int out_size)
{
    const float* x     = (const float*)d_in[0];
    const float* w_qkv = (const float*)d_in[1];
    const float* w_out = (const float*)d_in[2];
    const float* b_out = (const float*)d_in[3];
    float* out = (float*)d_out;

    u16 *p_xs_hi, *p_xs_lo, *p_wq_hi, *p_wq_lo, *p_wo_hi, *p_wo_lo;
    u16 *p_att_hi, *p_att_lo;
    cudaGetSymbolAddress((void**)&p_xs_hi, xs_hi);
    cudaGetSymbolAddress((void**)&p_xs_lo, xs_lo);
    cudaGetSymbolAddress((void**)&p_wq_hi, wq_hi);
    cudaGetSymbolAddress((void**)&p_wq_lo, wq_lo);
    cudaGetSymbolAddress((void**)&p_wo_hi, wo_hi);
    cudaGetSymbolAddress((void**)&p_wo_lo, wo_lo);
    cudaGetSymbolAddress((void**)&p_att_hi, att_hi);
    cudaGetSymbolAddress((void**)&p_att_lo, att_lo);

    cudaFuncSetAttribute(attn_mma,
                         cudaFuncAttributeMaxDynamicSharedMemorySize, ATTN_SMEM);
    cudaFuncSetAttribute(gemm_mma<0>,
                         cudaFuncAttributeMaxDynamicSharedMemorySize, GEMM_SMEM);
    cudaFuncSetAttribute(gemm_mma<1>,
                         cudaFuncAttributeMaxDynamicSharedMemorySize, GEMM_SMEM);

    // 0) split inputs into hi/lo fp16
    {
        int n2 = TOK * Hh / 2;
        split_pair<<<(n2 + 255) / 256, 256>>>(x, p_xs_hi, p_xs_lo, n2);
        n2 = QKV3 * Hh / 2;
        split_pair<<<(n2 + 255) / 256, 256>>>(w_qkv, p_wq_hi, p_wq_lo, n2);
        n2 = Hh * Hh / 2;
        split_pair<<<(n2 + 255) / 256, 256>>>(w_out, p_wo_hi, p_wo_lo, n2);
    }

    // 1) qkv projection -> q split / k hi / vt hi (transposed)
    gemm_mma<0><<<dim3(QKV3 / 64, TOK / 128), 256, GEMM_SMEM>>>(
        p_xs_hi, p_xs_lo, p_wq_hi, p_wq_lo, nullptr, nullptr, TOK, QKV3, Hh);

    // 2) merged banded + split-KV attention (one launch)
    attn_mma<<<dim3(32 + 2 * 8, NHh, Bb), 256, ATTN_SMEM>>>();
    // 2c) combine partials for heavy queries
    combine_partials<<<dim3(HQ, 16), 64>>>();

    // 3) out projection + bias
    gemm_mma<1><<<dim3(Hh / 64, TOK / 128), 256, GEMM_SMEM>>>(
        p_att_hi, p_att_lo, p_wo_hi, p_wo_lo, b_out, out, TOK, Hh, Hh);
}

// round 15
// speedup vs baseline: 1.5483x; 1.3286x over previous
#include <cuda_runtime.h>
#include <cuda_fp16.h>
#include <math.h>
#include <stdint.h>

#define Bb   2
#define Ss   4096
#define Hh   512
#define NHh  8
#define HDd  64
#define QKV3 1536
#define TOK  (Bb * Ss)          // 8192

typedef unsigned long long u64;
typedef unsigned int u32;
typedef unsigned short u16;

// ============================================================================
// Global scratch (allocation-free rule: __device__ globals)
// x split (hi+lo); weights unsplit fp16; q/k/vt unsplit fp16; att split.
// ============================================================================
__device__ u16 xs_hi[(size_t)TOK * Hh],  xs_lo[(size_t)TOK * Hh];
__device__ u16 wq_hi[(size_t)QKV3 * Hh];
__device__ u16 wo_hi[(size_t)Hh * Hh];
// per (b,h): q,k [4096,64] row-major ; vt [64,4096] d-major (all hi-only)
__device__ u16 q_hi [(size_t)16 * Ss * HDd];
__device__ u16 k_hi [(size_t)16 * Ss * HDd];
__device__ u16 vt_hi[(size_t)16 * Ss * HDd];
__device__ u16 att_hi[(size_t)TOK * Hh], att_lo[(size_t)TOK * Hh];
// split-KV partials for heavy queries (q < 256): 9 slots x 16 bh x 256 q
#define HQ 256
__device__ float part_o[(size_t)9 * 16 * HQ * 64];
__device__ float part_m[9 * 16 * HQ];
__device__ float part_l[9 * 16 * HQ];

// ============================================================================
// helpers
// ============================================================================
__device__ __forceinline__ u32 smem_u32(const void* p) {
    u32 a;
    asm("{ .reg .u64 t; cvta.to.shared.u64 t, %1; cvt.u32.u64 %0, t; }"
        : "=r"(a) : "l"(p));
    return a;
}
// split (a, b) into hi (packed f16x2: a->lo half, b->hi half) and lo residual
__device__ __forceinline__ void split2_f16(float a, float b, u32& hi, u32& lo) {
    __half2 hp = __floats2half2_rn(a, b);
    float ra = a - __half2float(__low2half(hp));
    float rb = b - __half2float(__high2half(hp));
    __half2 lp = __floats2half2_rn(ra, rb);
    hi = *reinterpret_cast<u32*>(&hp);
    lo = *reinterpret_cast<u32*>(&lp);
}
__device__ __forceinline__ u32 pack2_f16(float a, float b) {
    __half2 hp = __floats2half2_rn(a, b);
    return *reinterpret_cast<u32*>(&hp);
}
__device__ __forceinline__ void mma_f16(float* d, const u32* a, const u32* b) {
    asm volatile(
        "mma.sync.aligned.m16n8k16.row.col.f32.f16.f16.f32 "
        "{%0,%1,%2,%3}, {%4,%5,%6,%7}, {%8,%9}, {%0,%1,%2,%3};"
        : "+f"(d[0]), "+f"(d[1]), "+f"(d[2]), "+f"(d[3])
        : "r"(a[0]), "r"(a[1]), "r"(a[2]), "r"(a[3]), "r"(b[0]), "r"(b[1]));
}
__device__ __forceinline__ void ldsm4(u32* r, u32 addr) {
    asm volatile("ldmatrix.sync.aligned.m8n8.x4.shared.b16 {%0,%1,%2,%3}, [%4];"
        : "=r"(r[0]), "=r"(r[1]), "=r"(r[2]), "=r"(r[3]) : "r"(addr));
}
#define CP16(s, g) \
    asm volatile("cp.async.cg.shared.global [%0], [%1], 16;" \
                 :: "r"(s), "l"(g) : "memory")
#define CP_COMMIT() asm volatile("cp.async.commit_group;" ::: "memory")
#define CP_WAIT0()  asm volatile("cp.async.wait_group 0;" ::: "memory")
#define CP_WAIT1()  asm volatile("cp.async.wait_group 1;" ::: "memory")

// ============================================================================
// prep kernels: fp32 -> split (hi,lo) pair, and fp32 -> fp16 convert
// ============================================================================
__global__ void split_pair(const float* __restrict__ src,
                           u16* __restrict__ hi, u16* __restrict__ lo, int n2)
{
    int i = blockIdx.x * blockDim.x + threadIdx.x;
    if (i >= n2) return;
    u32 h, l;
    split2_f16(src[2 * i], src[2 * i + 1], h, l);
    ((u32*)hi)[i] = h;
    ((u32*)lo)[i] = l;
}
__global__ void cvt_f16(const float* __restrict__ src,
                        u16* __restrict__ dst, int n2)
{
    int i = blockIdx.x * blockDim.x + threadIdx.x;
    if (i >= n2) return;
    ((u32*)dst)[i] = pack2_f16(src[2 * i], src[2 * i + 1]);
}

// ============================================================================
// GEMM on mma.sync: C[M,N] = A[M,512] @ B[N,512]^T.
// A split fp16 (2-pass: ah*b + al*b); B unsplit fp16.
// 128x64 tile, BK=64, 256 threads / 8 warps. cp.async double-buffered.
// MODE 0: qkv epilogue -> q/k hi (row-major, q scaled 0.125), vt hi transposed
// MODE 1: fp32 out + bias
// Buffer: AHI 0 (18432)  ALO 18432 (18432)  BHI 36864 (9216) ; x2 = 92160
// ============================================================================
#define RB 144
#define G_AHI 0u
#define G_ALO 18432u
#define G_BHI 36864u
#define G_BUF 46080u
#define GEMM_SMEM 92160

template<int MODE>
__global__ __launch_bounds__(256, 2) void gemm_mma(
    const u16* __restrict__ Ah, const u16* __restrict__ Al,
    const u16* __restrict__ Bh,
    const float* __restrict__ bias, float* __restrict__ Cf,
    int M, int N, int K)
{
    extern __shared__ char sm[];
    const u32 smb = smem_u32(sm);
    const int tid = threadIdx.x;
    const int wid = tid >> 5;
    const int lid = tid & 31;
    const int g   = lid >> 2;
    const int qd  = lid & 3;
    const int m0  = blockIdx.y * 128;
    const int n0  = blockIdx.x * 64;

    const u32 a_row   = (u32)(16 * wid + (lid & 15));
    const u32 a_col16 = (u32)(((lid >> 4) & 1) << 4);
    const u32 aOffA   = a_row * RB + a_col16;
    const u32 bOff4 = (u32)((lid & 7) * RB + (((lid >> 3) & 1) << 4)
                            + (((lid >> 4) & 1) * 8 * RB));

    const int sr  = tid >> 3;
    const int sc  = tid & 7;

    float sf[8][4];
    #pragma unroll
    for (int n = 0; n < 8; n++)
        #pragma unroll
        for (int e = 0; e < 4; e++) sf[n][e] = 0.f;

    // prefetch chunk 0 into buffer 0
    {
        const u32 base = smb;
        #pragma unroll
        for (int i = 0; i < 4; i++) {
            int row = sr + i * 32;
            CP16(base + G_AHI + row * RB + sc * 16, &Ah[(size_t)(m0 + row) * K + sc * 8]);
            CP16(base + G_ALO + row * RB + sc * 16, &Al[(size_t)(m0 + row) * K + sc * 8]);
        }
        #pragma unroll
        for (int i = 0; i < 2; i++) {
            int row = sr + i * 32;
            CP16(base + G_BHI + row * RB + sc * 16, &Bh[(size_t)(n0 + row) * K + sc * 8]);
        }
        CP_COMMIT();
    }

    const int nk = K >> 6;
    for (int ck = 0; ck < nk; ck++) {
        const u32 cbase = smb + (u32)(ck & 1) * G_BUF;
        if (ck + 1 < nk) {
            const u32 nbase = smb + (u32)((ck + 1) & 1) * G_BUF;
            const int kc = (ck + 1) << 6;
            #pragma unroll
            for (int i = 0; i < 4; i++) {
                int row = sr + i * 32;
                CP16(nbase + G_AHI + row * RB + sc * 16, &Ah[(size_t)(m0 + row) * K + kc + sc * 8]);
                CP16(nbase + G_ALO + row * RB + sc * 16, &Al[(size_t)(m0 + row) * K + kc + sc * 8]);
            }
            #pragma unroll
            for (int i = 0; i < 2; i++) {
                int row = sr + i * 32;
                CP16(nbase + G_BHI + row * RB + sc * 16, &Bh[(size_t)(n0 + row) * K + kc + sc * 8]);
            }
            CP_COMMIT();
            CP_WAIT1();
        } else {
            CP_WAIT0();
        }
        __syncthreads();

        #pragma unroll
        for (int k = 0; k < 4; k++) {
            u32 ah[4], al[4];
            ldsm4(ah, cbase + G_AHI + aOffA + k * 32);
            ldsm4(al, cbase + G_ALO + aOffA + k * 32);
            u32 bh[16];
            #pragma unroll
            for (int q = 0; q < 4; q++)
                ldsm4(bh + 4 * q, cbase + G_BHI + (u32)(q * 16 * RB) + bOff4 + k * 32);
            #pragma unroll
            for (int n = 0; n < 8; n++) mma_f16(sf[n], ah, bh + 2 * n);
            #pragma unroll
            for (int n = 0; n < 8; n++) mma_f16(sf[n], al, bh + 2 * n);
        }
        __syncthreads();
    }

    if (MODE == 1) {
        const int row0 = m0 + 16 * wid + g;
        #pragma unroll
        for (int n = 0; n < 8; n++) {
            const int cg = n0 + 8 * n + 2 * qd;
            float bx = bias[cg], by = bias[cg + 1];
            *(float2*)&Cf[(size_t)row0 * N + cg] =
                make_float2(sf[n][0] + bx, sf[n][1] + by);
            *(float2*)&Cf[(size_t)(row0 + 8) * N + cg] =
                make_float2(sf[n][2] + bx, sf[n][3] + by);
        }
    } else {
        // ---- stage fp16 tile (hi-only) in smem, then scatter ----
        const float scale = (n0 < 512) ? 0.125f : 1.0f;   // q gets 1/sqrt(hd)
        const int prow0 = 16 * wid + g;
        #pragma unroll
        for (int n = 0; n < 8; n++) {
            u32 h0 = pack2_f16(sf[n][0] * scale, sf[n][1] * scale);
            u32 h1 = pack2_f16(sf[n][2] * scale, sf[n][3] * scale);
            u32 cb = (u32)(16 * n + 4 * qd);
            *(u32*)(sm + G_AHI + (u32)(prow0 * RB) + cb)       = h0;
            *(u32*)(sm + G_AHI + (u32)((prow0 + 8) * RB) + cb) = h1;
        }
        __syncthreads();

        const int type = n0 >> 9;                      // 0=q 1=k 2=v
        const int bhd  = (m0 >> 12) * 8 + ((n0 & 511) >> 6);
        const int s0   = m0 & 4095;

        if (type < 2) {
            u16* dh = (type == 0) ? q_hi : k_hi;
            #pragma unroll
            for (int i = 0; i < 4; i++) {
                int row = sr + i * 32;
                size_t d = ((size_t)bhd * Ss + s0 + row) * 64 + sc * 8;
                *(uint4*)&dh[d] = *(uint4*)(sm + G_AHI + row * RB + sc * 16);
            }
        } else {
            #pragma unroll
            for (int i = 0; i < 4; i++) {
                int t  = tid + i * 256;
                int d  = t >> 4, ch = t & 15;
                u16 th[8];
                #pragma unroll
                for (int j = 0; j < 8; j++)
                    th[j] = *(u16*)(sm + G_AHI + (ch * 8 + j) * RB + d * 2);
                size_t dst = ((size_t)bhd * 64 + d) * Ss + s0 + ch * 8;
                *(uint4*)&vt_hi[dst] = *(uint4*)th;
            }
        }
    }
}

// ============================================================================
// Flash attention on mma.sync, banded + split-KV, single merged launch.
// Fully fp16 operands (q, k, v, P unsplit): 1-pass QK + 1-pass PV.
// fp32 accumulation + fp32 softmax throughout.
// Bounds as round 11: band j<256 (4 tiles); heavy queries i<256 (qb 0,1).
// SMEM: KHI 0 (9216)  VTHI 9216 (9216)  QHI 18432 (18432)  tot 36864
// ============================================================================
#define OFF_KHI  0u
#define OFF_VTHI 9216u
#define OFF_QHI  18432u
#define ATTN_SMEM 36864

__global__ __launch_bounds__(256, 2) void attn_mma()
{
    extern __shared__ char sm[];
    const u32 smb = smem_u32(sm);
    const int tid = threadIdx.x;
    const int wid = tid >> 5;
    const int lid = tid & 31;
    const int g   = lid >> 2;
    const int qd  = lid & 3;

    int qb, kb0, kb1, slot;
    if (blockIdx.x < 32) {
        qb = blockIdx.x; kb0 = 0; kb1 = HQ; slot = 0;
    } else {
        const int t = blockIdx.x - 32;
        qb = t >> 3;
        const int c = t & 7;
        const int t0 = (c < 4) ? (4 + 8 * c) : (36 + 7 * (c - 4));
        const int t1 = t0 + ((c < 4) ? 8 : 7);
        kb0 = t0 * 64; kb1 = t1 * 64; slot = 1 + c;
    }
    const int qbase = qb * 128;
    const int h = blockIdx.y;
    const int b = blockIdx.z;
    const int bhd = b * 8 + h;

    const u16* qgh = q_hi + (size_t)bhd * Ss * 64;
    const u16* kgh = k_hi + (size_t)bhd * Ss * 64;
    const u16* vgh = vt_hi + (size_t)bhd * 64 * Ss;

    const int sr = tid >> 3;
    const int sc = tid & 7;

    // ---- Q staging (cp.async, once, hi-only) ----
    #pragma unroll
    for (int i = 0; i < 4; i++) {
        int row = sr + i * 32;
        CP16(smb + OFF_QHI + row * RB + sc * 16,
             &qgh[(size_t)(qbase + row) * 64 + sc * 8]);
    }

    const u32 a_row   = (u32)(16 * wid + (lid & 15));
    const u32 a_col16 = (u32)(((lid >> 4) & 1) << 4);
    const u32 aQhi = smb + OFF_QHI + a_row * RB + a_col16;
    const u32 bOff4 = (u32)((lid & 7) * RB + (((lid >> 3) & 1) << 4)
                            + (((lid >> 4) & 1) * 8 * RB));

    float o[8][4];
    #pragma unroll
    for (int n = 0; n < 8; n++)
        #pragma unroll
        for (int e = 0; e < 4; e++) o[n][e] = 0.f;
    float m0 = -1e30f, m1 = -1e30f, l0 = 0.f, l1 = 0.f;
    const float LOGD = -0.10536051565782628f;   // log(0.9)
    const int iq0 = qbase + 16 * wid + g;

    for (int kb = kb0; kb < kb1; kb += 64) {
        // ---- K / VT staging ----
        #pragma unroll
        for (int i = 0; i < 2; i++) {
            int row = sr + i * 32;
            CP16(smb + OFF_KHI + row * RB + sc * 16,
                 &kgh[(size_t)(kb + row) * 64 + sc * 8]);
            CP16(smb + OFF_VTHI + row * RB + sc * 16,
                 &vgh[(size_t)row * Ss + kb + sc * 8]);
        }
        CP_COMMIT();
        CP_WAIT0();
        __syncthreads();

        // ---- S = Q K^T : single pass ----
        float sf[8][4];
        #pragma unroll
        for (int n = 0; n < 8; n++)
            #pragma unroll
            for (int e = 0; e < 4; e++) sf[n][e] = 0.f;

        #pragma unroll
        for (int k = 0; k < 4; k++) {
            u32 ah[4];
            ldsm4(ah, aQhi + k * 32);
            u32 bh[16];
            #pragma unroll
            for (int q = 0; q < 4; q++)
                ldsm4(bh + 4 * q, smb + OFF_KHI + (u32)(q * 16 * RB) + bOff4 + k * 32);
            #pragma unroll
            for (int n = 0; n < 8; n++) mma_f16(sf[n], ah, bh + 2 * n);
        }

        // ---- bias + online softmax ----
        const float base0 = (float)(kb - iq0);
        float rmax0 = -1e30f, rmax1 = -1e30f;
        #pragma unroll
        for (int n = 0; n < 8; n++) {
            #pragma unroll
            for (int e = 0; e < 2; e++) {
                float c = (float)(8 * n + 2 * qd + e);
                float t0 = sf[n][e]     + fmaxf((base0 + c) * LOGD, 0.0f);
                float t1 = sf[n][2 + e] + fmaxf((base0 - 8.0f + c) * LOGD, 0.0f);
                sf[n][e] = t0; sf[n][2 + e] = t1;
                rmax0 = fmaxf(rmax0, t0);
                rmax1 = fmaxf(rmax1, t1);
            }
        }
        rmax0 = fmaxf(rmax0, __shfl_xor_sync(0xffffffffu, rmax0, 1));
        rmax0 = fmaxf(rmax0, __shfl_xor_sync(0xffffffffu, rmax0, 2));
        rmax1 = fmaxf(rmax1, __shfl_xor_sync(0xffffffffu, rmax1, 1));
        rmax1 = fmaxf(rmax1, __shfl_xor_sync(0xffffffffu, rmax1, 2));

        float mn0 = fmaxf(m0, rmax0), mn1 = fmaxf(m1, rmax1);
        float corr0 = __expf(m0 - mn0), corr1 = __expf(m1 - mn1);
        m0 = mn0; m1 = mn1;

        float rs0 = 0.f, rs1 = 0.f;
        #pragma unroll
        for (int n = 0; n < 8; n++) {
            sf[n][0] = __expf(sf[n][0] - mn0);
            sf[n][1] = __expf(sf[n][1] - mn0);
            sf[n][2] = __expf(sf[n][2] - mn1);
            sf[n][3] = __expf(sf[n][3] - mn1);
            rs0 += sf[n][0] + sf[n][1];
            rs1 += sf[n][2] + sf[n][3];
        }
        rs0 += __shfl_xor_sync(0xffffffffu, rs0, 1);
        rs0 += __shfl_xor_sync(0xffffffffu, rs0, 2);
        rs1 += __shfl_xor_sync(0xffffffffu, rs1, 1);
        rs1 += __shfl_xor_sync(0xffffffffu, rs1, 2);
        l0 = l0 * corr0 + rs0;
        l1 = l1 * corr1 + rs1;

        #pragma unroll
        for (int n = 0; n < 8; n++) {
            o[n][0] *= corr0; o[n][1] *= corr0;
            o[n][2] *= corr1; o[n][3] *= corr1;
        }

        // ---- O += P V : single pass, P packed fp16 register-direct ----
        #pragma unroll
        for (int kk = 0; kk < 4; kk++) {
            u32 ph[4];
            ph[0] = pack2_f16(sf[2*kk][0],   sf[2*kk][1]);
            ph[1] = pack2_f16(sf[2*kk][2],   sf[2*kk][3]);
            ph[2] = pack2_f16(sf[2*kk+1][0], sf[2*kk+1][1]);
            ph[3] = pack2_f16(sf[2*kk+1][2], sf[2*kk+1][3]);
            u32 vh[16];
            #pragma unroll
            for (int q = 0; q < 4; q++)
                ldsm4(vh + 4 * q, smb + OFF_VTHI + (u32)(q * 16 * RB) + bOff4 + kk * 32);
            #pragma unroll
            for (int n = 0; n < 8; n++) mma_f16(o[n], ph, vh + 2 * n);
        }
        __syncthreads();
    }

    if (blockIdx.x < 32 && qbase >= HQ) {
        // ---- final: normalize, split, write att hi/lo ----
        const float inv0 = 1.0f / l0, inv1 = 1.0f / l1;
        const size_t r0 = ((size_t)(b * Ss + iq0)) * Hh + h * HDd;
        const size_t r1 = r0 + (size_t)8 * Hh;
        #pragma unroll
        for (int n = 0; n < 8; n++) {
            int col = 8 * n + 2 * qd;
            u32 h0, l0w, h1, l1w;
            split2_f16(o[n][0] * inv0, o[n][1] * inv0, h0, l0w);
            split2_f16(o[n][2] * inv1, o[n][3] * inv1, h1, l1w);
            *(u32*)&att_hi[r0 + col] = h0;
            *(u32*)&att_lo[r0 + col] = l0w;
            *(u32*)&att_hi[r1 + col] = h1;
            *(u32*)&att_lo[r1 + col] = l1w;
        }
    } else {
        // ---- partial: write unnormalized o + (m, l) to slot ----
        const size_t rb0 = ((size_t)(slot * 16 + bhd) * HQ + iq0) * 64;
        const size_t rb1 = rb0 + (size_t)8 * 64;
        #pragma unroll
        for (int n = 0; n < 8; n++) {
            int col = 8 * n + 2 * qd;
            *(float2*)&part_o[rb0 + col] = make_float2(o[n][0], o[n][1]);
            *(float2*)&part_o[rb1 + col] = make_float2(o[n][2], o[n][3]);
        }
        if (qd == 0) {
            const int mi = (slot * 16 + bhd) * HQ + iq0;
            part_m[mi]     = m0; part_l[mi]     = l0;
            part_m[mi + 8] = m1; part_l[mi + 8] = l1;
        }
    }
}

// ============================================================================
// combine 9 split-KV partials per heavy query row -> att hi/lo
// grid (HQ, 16), block 64 (one thread per dim)
// ============================================================================
__global__ void combine_partials()
{
    const int q   = blockIdx.x;
    const int bhd = blockIdx.y;
    const int d   = threadIdx.x;

    float mm[9], ll[9];
    float M = -1e30f;
    #pragma unroll
    for (int s = 0; s < 9; s++) {
        mm[s] = part_m[(s * 16 + bhd) * HQ + q];
        ll[s] = part_l[(s * 16 + bhd) * HQ + q];
        M = fmaxf(M, mm[s]);
    }
    float L = 0.f, acc = 0.f;
    #pragma unroll
    for (int s = 0; s < 9; s++) {
        float e = __expf(mm[s] - M);
        L += ll[s] * e;
        acc += part_o[((size_t)(s * 16 + bhd) * HQ + q) * 64 + d] * e;
    }
    float a = acc / L;

    const int b = bhd >> 3, h = bhd & 7;
    const size_t idx = ((size_t)(b * Ss + q)) * Hh + h * HDd + d;
    __half hh = __float2half_rn(a);
    float r = a - __half2float(hh);
    att_hi[idx] = __half_as_ushort(hh);
    att_lo[idx] = __half_as_ushort(__float2half_rn(r));
}

// ============================================================================

extern "C" void kernel_launch(void* const* d_in, const int* in_sizes, int n_in,
                              void* d_out, int out_size)
{
    const float* x     = (const float*)d_in[0];
    const float* w_qkv = (const float*)d_in[1];
    const float* w_out = (const float*)d_in[2];
    const float* b_out = (const float*)d_in[3];
    float* out = (float*)d_out;

    u16 *p_xs_hi, *p_xs_lo, *p_wq_hi, *p_wo_hi, *p_att_hi, *p_att_lo;
    cudaGetSymbolAddress((void**)&p_xs_hi, xs_hi);
    cudaGetSymbolAddress((void**)&p_xs_lo, xs_lo);
    cudaGetSymbolAddress((void**)&p_wq_hi, wq_hi);
    cudaGetSymbolAddress((void**)&p_wo_hi, wo_hi);
    cudaGetSymbolAddress((void**)&p_att_hi, att_hi);
    cudaGetSymbolAddress((void**)&p_att_lo, att_lo);

    cudaFuncSetAttribute(attn_mma,
                         cudaFuncAttributeMaxDynamicSharedMemorySize, ATTN_SMEM);
    cudaFuncSetAttribute(gemm_mma<0>,
                         cudaFuncAttributeMaxDynamicSharedMemorySize, GEMM_SMEM);
    cudaFuncSetAttribute(gemm_mma<1>,
                         cudaFuncAttributeMaxDynamicSharedMemorySize, GEMM_SMEM);

    // 0) x -> split hi/lo ; weights -> fp16
    {
        int n2 = TOK * Hh / 2;
        split_pair<<<(n2 + 255) / 256, 256>>>(x, p_xs_hi, p_xs_lo, n2);
        n2 = QKV3 * Hh / 2;
        cvt_f16<<<(n2 + 255) / 256, 256>>>(w_qkv, p_wq_hi, n2);
        n2 = Hh * Hh / 2;
        cvt_f16<<<(n2 + 255) / 256, 256>>>(w_out, p_wo_hi, n2);
    }

    // 1) qkv projection (2-pass) -> q/k hi (row-major) + vt hi (transposed)
    gemm_mma<0><<<dim3(QKV3 / 64, TOK / 128), 256, GEMM_SMEM>>>(
        p_xs_hi, p_xs_lo, p_wq_hi, nullptr, nullptr, TOK, QKV3, Hh);

    // 2) merged banded + split-KV attention (one launch)
    attn_mma<<<dim3(32 + 2 * 8, NHh, Bb), 256, ATTN_SMEM>>>();
    // 2c) combine partials for heavy queries
    combine_partials<<<dim3(HQ, 16), 64>>>();

    // 3) out projection (2-pass) + bias
    gemm_mma<1><<<dim3(Hh / 64, TOK / 128), 256, GEMM_SMEM>>>(
        p_att_hi, p_att_lo, p_wo_hi, b_out, out, TOK, Hh, Hh);
}

// round 16
// speedup vs baseline: 1.9129x; 1.2355x over previous
#include <cuda_runtime.h>
#include <cuda_fp16.h>
#include <math.h>
#include <stdint.h>

#define Bb   2
#define Ss   4096
#define Hh   512
#define NHh  8
#define HDd  64
#define QKV3 1536
#define TOK  (Bb * Ss)          // 8192

typedef unsigned long long u64;
typedef unsigned int u32;
typedef unsigned short u16;

// ============================================================================
// Global scratch (allocation-free rule: __device__ globals) — all plain fp16
// ============================================================================
__device__ u16 xs_hi[(size_t)TOK * Hh];
__device__ u16 wq_hi[(size_t)QKV3 * Hh];
__device__ u16 wo_hi[(size_t)Hh * Hh];
// per (b,h): q,k [4096,64] row-major ; vt [64,4096] d-major
__device__ u16 q_hi [(size_t)16 * Ss * HDd];
__device__ u16 k_hi [(size_t)16 * Ss * HDd];
__device__ u16 vt_hi[(size_t)16 * Ss * HDd];
__device__ u16 att_hi[(size_t)TOK * Hh];
// split-KV partials for heavy queries (q < 256): 9 slots x 16 bh x 256 q
#define HQ 256
__device__ float part_o[(size_t)9 * 16 * HQ * 64];
__device__ float part_m[9 * 16 * HQ];
__device__ float part_l[9 * 16 * HQ];

// ============================================================================
// helpers
// ============================================================================
__device__ __forceinline__ u32 smem_u32(const void* p) {
    u32 a;
    asm("{ .reg .u64 t; cvta.to.shared.u64 t, %1; cvt.u32.u64 %0, t; }"
        : "=r"(a) : "l"(p));
    return a;
}
__device__ __forceinline__ u32 pack2_f16(float a, float b) {
    __half2 hp = __floats2half2_rn(a, b);
    return *reinterpret_cast<u32*>(&hp);
}
__device__ __forceinline__ void mma_f16(float* d, const u32* a, const u32* b) {
    asm volatile(
        "mma.sync.aligned.m16n8k16.row.col.f32.f16.f16.f32 "
        "{%0,%1,%2,%3}, {%4,%5,%6,%7}, {%8,%9}, {%0,%1,%2,%3};"
        : "+f"(d[0]), "+f"(d[1]), "+f"(d[2]), "+f"(d[3])
        : "r"(a[0]), "r"(a[1]), "r"(a[2]), "r"(a[3]), "r"(b[0]), "r"(b[1]));
}
__device__ __forceinline__ void ldsm4(u32* r, u32 addr) {
    asm volatile("ldmatrix.sync.aligned.m8n8.x4.shared.b16 {%0,%1,%2,%3}, [%4];"
        : "=r"(r[0]), "=r"(r[1]), "=r"(r[2]), "=r"(r[3]) : "r"(addr));
}
#define CP16(s, g) \
    asm volatile("cp.async.cg.shared.global [%0], [%1], 16;" \
                 :: "r"(s), "l"(g) : "memory")
#define CP_COMMIT() asm volatile("cp.async.commit_group;" ::: "memory")
#define CP_WAIT0()  asm volatile("cp.async.wait_group 0;" ::: "memory")
#define CP_WAIT1()  asm volatile("cp.async.wait_group 1;" ::: "memory")

// ============================================================================
// prep kernel: fp32 -> fp16
// ============================================================================
__global__ void cvt_f16(const float* __restrict__ src,
                        u16* __restrict__ dst, int n2)
{
    int i = blockIdx.x * blockDim.x + threadIdx.x;
    if (i >= n2) return;
    ((u32*)dst)[i] = pack2_f16(src[2 * i], src[2 * i + 1]);
}

// ============================================================================
// GEMM on mma.sync: C[M,N] = A[M,512] @ B[N,512]^T, fp16 operands,
// fp32 accumulation, single pass. 128x64 tile, BK=64, 256 threads / 8 warps.
// cp.async double-buffered.
// MODE 0: qkv epilogue -> q/k (row-major, q scaled 0.125), vt transposed
// MODE 1: fp32 out + bias
// Buffer: A 0 (18432)  B 18432 (9216) ; x2 buffers = 55296
// ============================================================================
#define RB 144
#define G_A   0u
#define G_B   18432u
#define G_BUF 27648u
#define GEMM_SMEM 55296

template<int MODE>
__global__ __launch_bounds__(256, 2) void gemm_mma(
    const u16* __restrict__ Ah, const u16* __restrict__ Bh,
    const float* __restrict__ bias, float* __restrict__ Cf,
    int M, int N, int K)
{
    extern __shared__ char sm[];
    const u32 smb = smem_u32(sm);
    const int tid = threadIdx.x;
    const int wid = tid >> 5;
    const int lid = tid & 31;
    const int g   = lid >> 2;
    const int qd  = lid & 3;
    const int m0  = blockIdx.y * 128;
    const int n0  = blockIdx.x * 64;

    const u32 a_row   = (u32)(16 * wid + (lid & 15));
    const u32 a_col16 = (u32)(((lid >> 4) & 1) << 4);
    const u32 aOffA   = a_row * RB + a_col16;
    const u32 bOff4 = (u32)((lid & 7) * RB + (((lid >> 3) & 1) << 4)
                            + (((lid >> 4) & 1) * 8 * RB));

    const int sr  = tid >> 3;
    const int sc  = tid & 7;

    float sf[8][4];
    #pragma unroll
    for (int n = 0; n < 8; n++)
        #pragma unroll
        for (int e = 0; e < 4; e++) sf[n][e] = 0.f;

    // prefetch chunk 0 into buffer 0
    {
        #pragma unroll
        for (int i = 0; i < 4; i++) {
            int row = sr + i * 32;
            CP16(smb + G_A + row * RB + sc * 16, &Ah[(size_t)(m0 + row) * K + sc * 8]);
        }
        #pragma unroll
        for (int i = 0; i < 2; i++) {
            int row = sr + i * 32;
            CP16(smb + G_B + row * RB + sc * 16, &Bh[(size_t)(n0 + row) * K + sc * 8]);
        }
        CP_COMMIT();
    }

    const int nk = K >> 6;
    for (int ck = 0; ck < nk; ck++) {
        const u32 cbase = smb + (u32)(ck & 1) * G_BUF;
        if (ck + 1 < nk) {
            const u32 nbase = smb + (u32)((ck + 1) & 1) * G_BUF;
            const int kc = (ck + 1) << 6;
            #pragma unroll
            for (int i = 0; i < 4; i++) {
                int row = sr + i * 32;
                CP16(nbase + G_A + row * RB + sc * 16, &Ah[(size_t)(m0 + row) * K + kc + sc * 8]);
            }
            #pragma unroll
            for (int i = 0; i < 2; i++) {
                int row = sr + i * 32;
                CP16(nbase + G_B + row * RB + sc * 16, &Bh[(size_t)(n0 + row) * K + kc + sc * 8]);
            }
            CP_COMMIT();
            CP_WAIT1();
        } else {
            CP_WAIT0();
        }
        __syncthreads();

        #pragma unroll
        for (int k = 0; k < 4; k++) {
            u32 ah[4];
            ldsm4(ah, cbase + G_A + aOffA + k * 32);
            u32 bh[16];
            #pragma unroll
            for (int q = 0; q < 4; q++)
                ldsm4(bh + 4 * q, cbase + G_B + (u32)(q * 16 * RB) + bOff4 + k * 32);
            #pragma unroll
            for (int n = 0; n < 8; n++) mma_f16(sf[n], ah, bh + 2 * n);
        }
        __syncthreads();
    }

    if (MODE == 1) {
        const int row0 = m0 + 16 * wid + g;
        #pragma unroll
        for (int n = 0; n < 8; n++) {
            const int cg = n0 + 8 * n + 2 * qd;
            float bx = bias[cg], by = bias[cg + 1];
            *(float2*)&Cf[(size_t)row0 * N + cg] =
                make_float2(sf[n][0] + bx, sf[n][1] + by);
            *(float2*)&Cf[(size_t)(row0 + 8) * N + cg] =
                make_float2(sf[n][2] + bx, sf[n][3] + by);
        }
    } else {
        // ---- stage fp16 tile in smem (buffer-0 A region), then scatter ----
        const float scale = (n0 < 512) ? 0.125f : 1.0f;   // q gets 1/sqrt(hd)
        const int prow0 = 16 * wid + g;
        #pragma unroll
        for (int n = 0; n < 8; n++) {
            u32 h0 = pack2_f16(sf[n][0] * scale, sf[n][1] * scale);
            u32 h1 = pack2_f16(sf[n][2] * scale, sf[n][3] * scale);
            u32 cb = (u32)(16 * n + 4 * qd);
            *(u32*)(sm + G_A + (u32)(prow0 * RB) + cb)       = h0;
            *(u32*)(sm + G_A + (u32)((prow0 + 8) * RB) + cb) = h1;
        }
        __syncthreads();

        const int type = n0 >> 9;                      // 0=q 1=k 2=v
        const int bhd  = (m0 >> 12) * 8 + ((n0 & 511) >> 6);
        const int s0   = m0 & 4095;

        if (type < 2) {
            u16* dh = (type == 0) ? q_hi : k_hi;
            #pragma unroll
            for (int i = 0; i < 4; i++) {
                int row = sr + i * 32;
                size_t d = ((size_t)bhd * Ss + s0 + row) * 64 + sc * 8;
                *(uint4*)&dh[d] = *(uint4*)(sm + G_A + row * RB + sc * 16);
            }
        } else {
            #pragma unroll
            for (int i = 0; i < 4; i++) {
                int t  = tid + i * 256;
                int d  = t >> 4, ch = t & 15;
                u16 th[8];
                #pragma unroll
                for (int j = 0; j < 8; j++)
                    th[j] = *(u16*)(sm + G_A + (ch * 8 + j) * RB + d * 2);
                size_t dst = ((size_t)bhd * 64 + d) * Ss + s0 + ch * 8;
                *(uint4*)&vt_hi[dst] = *(uint4*)th;
            }
        }
    }
}

// ============================================================================
// Flash attention on mma.sync, banded + split-KV, single merged launch.
// fp16 operands, fp32 accumulation + fp32 softmax.
// Bounds: band j<256 (4 tiles); heavy queries i<256 (qb 0,1) need tiles 4..63.
// SMEM: K 0 (9216)  VT 9216 (9216)  Q 18432 (18432)  tot 36864
// ============================================================================
#define OFF_KHI  0u
#define OFF_VTHI 9216u
#define OFF_QHI  18432u
#define ATTN_SMEM 36864

__global__ __launch_bounds__(256, 2) void attn_mma()
{
    extern __shared__ char sm[];
    const u32 smb = smem_u32(sm);
    const int tid = threadIdx.x;
    const int wid = tid >> 5;
    const int lid = tid & 31;
    const int g   = lid >> 2;
    const int qd  = lid & 3;

    int qb, kb0, kb1, slot;
    if (blockIdx.x < 32) {
        qb = blockIdx.x; kb0 = 0; kb1 = HQ; slot = 0;
    } else {
        const int t = blockIdx.x - 32;
        qb = t >> 3;
        const int c = t & 7;
        const int t0 = (c < 4) ? (4 + 8 * c) : (36 + 7 * (c - 4));
        const int t1 = t0 + ((c < 4) ? 8 : 7);
        kb0 = t0 * 64; kb1 = t1 * 64; slot = 1 + c;
    }
    const int qbase = qb * 128;
    const int h = blockIdx.y;
    const int b = blockIdx.z;
    const int bhd = b * 8 + h;

    const u16* qgh = q_hi + (size_t)bhd * Ss * 64;
    const u16* kgh = k_hi + (size_t)bhd * Ss * 64;
    const u16* vgh = vt_hi + (size_t)bhd * 64 * Ss;

    const int sr = tid >> 3;
    const int sc = tid & 7;

    // ---- Q staging (cp.async, once) ----
    #pragma unroll
    for (int i = 0; i < 4; i++) {
        int row = sr + i * 32;
        CP16(smb + OFF_QHI + row * RB + sc * 16,
             &qgh[(size_t)(qbase + row) * 64 + sc * 8]);
    }

    const u32 a_row   = (u32)(16 * wid + (lid & 15));
    const u32 a_col16 = (u32)(((lid >> 4) & 1) << 4);
    const u32 aQhi = smb + OFF_QHI + a_row * RB + a_col16;
    const u32 bOff4 = (u32)((lid & 7) * RB + (((lid >> 3) & 1) << 4)
                            + (((lid >> 4) & 1) * 8 * RB));

    float o[8][4];
    #pragma unroll
    for (int n = 0; n < 8; n++)
        #pragma unroll
        for (int e = 0; e < 4; e++) o[n][e] = 0.f;
    float m0 = -1e30f, m1 = -1e30f, l0 = 0.f, l1 = 0.f;
    const float LOGD = -0.10536051565782628f;   // log(0.9)
    const int iq0 = qbase + 16 * wid + g;

    for (int kb = kb0; kb < kb1; kb += 64) {
        // ---- K / VT staging ----
        #pragma unroll
        for (int i = 0; i < 2; i++) {
            int row = sr + i * 32;
            CP16(smb + OFF_KHI + row * RB + sc * 16,
                 &kgh[(size_t)(kb + row) * 64 + sc * 8]);
            CP16(smb + OFF_VTHI + row * RB + sc * 16,
                 &vgh[(size_t)row * Ss + kb + sc * 8]);
        }
        CP_COMMIT();
        CP_WAIT0();
        __syncthreads();

        // ---- S = Q K^T : single pass ----
        float sf[8][4];
        #pragma unroll
        for (int n = 0; n < 8; n++)
            #pragma unroll
            for (int e = 0; e < 4; e++) sf[n][e] = 0.f;

        #pragma unroll
        for (int k = 0; k < 4; k++) {
            u32 ah[4];
            ldsm4(ah, aQhi + k * 32);
            u32 bh[16];
            #pragma unroll
            for (int q = 0; q < 4; q++)
                ldsm4(bh + 4 * q, smb + OFF_KHI + (u32)(q * 16 * RB) + bOff4 + k * 32);
            #pragma unroll
            for (int n = 0; n < 8; n++) mma_f16(sf[n], ah, bh + 2 * n);
        }

        // ---- bias + online softmax ----
        const float base0 = (float)(kb - iq0);
        float rmax0 = -1e30f, rmax1 = -1e30f;
        #pragma unroll
        for (int n = 0; n < 8; n++) {
            #pragma unroll
            for (int e = 0; e < 2; e++) {
                float c = (float)(8 * n + 2 * qd + e);
                float t0 = sf[n][e]     + fmaxf((base0 + c) * LOGD, 0.0f);
                float t1 = sf[n][2 + e] + fmaxf((base0 - 8.0f + c) * LOGD, 0.0f);
                sf[n][e] = t0; sf[n][2 + e] = t1;
                rmax0 = fmaxf(rmax0, t0);
                rmax1 = fmaxf(rmax1, t1);
            }
        }
        rmax0 = fmaxf(rmax0, __shfl_xor_sync(0xffffffffu, rmax0, 1));
        rmax0 = fmaxf(rmax0, __shfl_xor_sync(0xffffffffu, rmax0, 2));
        rmax1 = fmaxf(rmax1, __shfl_xor_sync(0xffffffffu, rmax1, 1));
        rmax1 = fmaxf(rmax1, __shfl_xor_sync(0xffffffffu, rmax1, 2));

        float mn0 = fmaxf(m0, rmax0), mn1 = fmaxf(m1, rmax1);
        float corr0 = __expf(m0 - mn0), corr1 = __expf(m1 - mn1);
        m0 = mn0; m1 = mn1;

        float rs0 = 0.f, rs1 = 0.f;
        #pragma unroll
        for (int n = 0; n < 8; n++) {
            sf[n][0] = __expf(sf[n][0] - mn0);
            sf[n][1] = __expf(sf[n][1] - mn0);
            sf[n][2] = __expf(sf[n][2] - mn1);
            sf[n][3] = __expf(sf[n][3] - mn1);
            rs0 += sf[n][0] + sf[n][1];
            rs1 += sf[n][2] + sf[n][3];
        }
        rs0 += __shfl_xor_sync(0xffffffffu, rs0, 1);
        rs0 += __shfl_xor_sync(0xffffffffu, rs0, 2);
        rs1 += __shfl_xor_sync(0xffffffffu, rs1, 1);
        rs1 += __shfl_xor_sync(0xffffffffu, rs1, 2);
        l0 = l0 * corr0 + rs0;
        l1 = l1 * corr1 + rs1;

        #pragma unroll
        for (int n = 0; n < 8; n++) {
            o[n][0] *= corr0; o[n][1] *= corr0;
            o[n][2] *= corr1; o[n][3] *= corr1;
        }

        // ---- O += P V : single pass, P packed fp16 register-direct ----
        #pragma unroll
        for (int kk = 0; kk < 4; kk++) {
            u32 ph[4];
            ph[0] = pack2_f16(sf[2*kk][0],   sf[2*kk][1]);
            ph[1] = pack2_f16(sf[2*kk][2],   sf[2*kk][3]);
            ph[2] = pack2_f16(sf[2*kk+1][0], sf[2*kk+1][1]);
            ph[3] = pack2_f16(sf[2*kk+1][2], sf[2*kk+1][3]);
            u32 vh[16];
            #pragma unroll
            for (int q = 0; q < 4; q++)
                ldsm4(vh + 4 * q, smb + OFF_VTHI + (u32)(q * 16 * RB) + bOff4 + kk * 32);
            #pragma unroll
            for (int n = 0; n < 8; n++) mma_f16(o[n], ph, vh + 2 * n);
        }
        __syncthreads();
    }

    if (blockIdx.x < 32 && qbase >= HQ) {
        // ---- final: normalize, write att fp16 ----
        const float inv0 = 1.0f / l0, inv1 = 1.0f / l1;
        const size_t r0 = ((size_t)(b * Ss + iq0)) * Hh + h * HDd;
        const size_t r1 = r0 + (size_t)8 * Hh;
        #pragma unroll
        for (int n = 0; n < 8; n++) {
            int col = 8 * n + 2 * qd;
            *(u32*)&att_hi[r0 + col] = pack2_f16(o[n][0] * inv0, o[n][1] * inv0);
            *(u32*)&att_hi[r1 + col] = pack2_f16(o[n][2] * inv1, o[n][3] * inv1);
        }
    } else {
        // ---- partial: write unnormalized o + (m, l) to slot ----
        const size_t rb0 = ((size_t)(slot * 16 + bhd) * HQ + iq0) * 64;
        const size_t rb1 = rb0 + (size_t)8 * 64;
        #pragma unroll
        for (int n = 0; n < 8; n++) {
            int col = 8 * n + 2 * qd;
            *(float2*)&part_o[rb0 + col] = make_float2(o[n][0], o[n][1]);
            *(float2*)&part_o[rb1 + col] = make_float2(o[n][2], o[n][3]);
        }
        if (qd == 0) {
            const int mi = (slot * 16 + bhd) * HQ + iq0;
            part_m[mi]     = m0; part_l[mi]     = l0;
            part_m[mi + 8] = m1; part_l[mi + 8] = l1;
        }
    }
}

// ============================================================================
// combine 9 split-KV partials per heavy query row -> att fp16
// grid (HQ, 16), block 64 (one thread per dim)
// ============================================================================
__global__ void combine_partials()
{
    const int q   = blockIdx.x;
    const int bhd = blockIdx.y;
    const int d   = threadIdx.x;

    float mm[9], ll[9];
    float M = -1e30f;
    #pragma unroll
    for (int s = 0; s < 9; s++) {
        mm[s] = part_m[(s * 16 + bhd) * HQ + q];
        ll[s] = part_l[(s * 16 + bhd) * HQ + q];
        M = fmaxf(M, mm[s]);
    }
    float L = 0.f, acc = 0.f;
    #pragma unroll
    for (int s = 0; s < 9; s++) {
        float e = __expf(mm[s] - M);
        L += ll[s] * e;
        acc += part_o[((size_t)(s * 16 + bhd) * HQ + q) * 64 + d] * e;
    }
    float a = acc / L;

    const int b = bhd >> 3, h = bhd & 7;
    const size_t idx = ((size_t)(b * Ss + q)) * Hh + h * HDd + d;
    att_hi[idx] = __half_as_ushort(__float2half_rn(a));
}

// ============================================================================

extern "C" void kernel_launch(void* const* d_in, const int* in_sizes, int n_in,
                              void* d_out, int out_size)
{
    const float* x     = (const float*)d_in[0];
    const float* w_qkv = (const float*)d_in[1];
    const float* w_out = (const float*)d_in[2];
    const float* b_out = (const float*)d_in[3];
    float* out = (float*)d_out;

    u16 *p_xs_hi, *p_wq_hi, *p_wo_hi, *p_att_hi;
    cudaGetSymbolAddress((void**)&p_xs_hi, xs_hi);
    cudaGetSymbolAddress((void**)&p_wq_hi, wq_hi);
    cudaGetSymbolAddress((void**)&p_wo_hi, wo_hi);
    cudaGetSymbolAddress((void**)&p_att_hi, att_hi);

    cudaFuncSetAttribute(attn_mma,
                         cudaFuncAttributeMaxDynamicSharedMemorySize, ATTN_SMEM);
    cudaFuncSetAttribute(gemm_mma<0>,
                         cudaFuncAttributeMaxDynamicSharedMemorySize, GEMM_SMEM);
    cudaFuncSetAttribute(gemm_mma<1>,
                         cudaFuncAttributeMaxDynamicSharedMemorySize, GEMM_SMEM);

    // 0) x, weights -> fp16
    {
        int n2 = TOK * Hh / 2;
        cvt_f16<<<(n2 + 255) / 256, 256>>>(x, p_xs_hi, n2);
        n2 = QKV3 * Hh / 2;
        cvt_f16<<<(n2 + 255) / 256, 256>>>(w_qkv, p_wq_hi, n2);
        n2 = Hh * Hh / 2;
        cvt_f16<<<(n2 + 255) / 256, 256>>>(w_out, p_wo_hi, n2);
    }

    // 1) qkv projection (1-pass) -> q/k (row-major) + vt (transposed)
    gemm_mma<0><<<dim3(QKV3 / 64, TOK / 128), 256, GEMM_SMEM>>>(
        p_xs_hi, p_wq_hi, nullptr, nullptr, TOK, QKV3, Hh);

    // 2) merged banded + split-KV attention (one launch)
    attn_mma<<<dim3(32 + 2 * 8, NHh, Bb), 256, ATTN_SMEM>>>();
    // 2c) combine partials for heavy queries
    combine_partials<<<dim3(HQ, 16), 64>>>();

    // 3) out projection (1-pass) + bias
    gemm_mma<1><<<dim3(Hh / 64, TOK / 128), 256, GEMM_SMEM>>>(
        p_att_hi, p_wo_hi, b_out, out, TOK, Hh, Hh);
}